// round 5
// baseline (speedup 1.0000x reference)
#include <cuda_runtime.h>
#include <cuda_bf16.h>
#include <cstdint>
#include <cstddef>

static constexpr int Bn = 8;
static constexpr int Cc = 512;
static constexpr int Nn = 4096;   // H*W
static constexpr int Kd = 64;
static constexpr int Vd = 512;

// Scratch (device globals)
__device__ __nv_bfloat16 g_Qh[(size_t)Bn * Nn * Kd];   // [b][n][k] bf16 hi
__device__ __nv_bfloat16 g_Ql[(size_t)Bn * Nn * Kd];   // bf16 residual lo
__device__ __nv_bfloat16 g_Kh[(size_t)Bn * Nn * Kd];
__device__ __nv_bfloat16 g_Kl[(size_t)Bn * Nn * Kd];
__device__ float g_Vm[(size_t)Bn * Nn * Vd];   // [b][m][v], tf32-rounded
__device__ float g_P [(size_t)Bn * Nn * Nn];   // exp(energy), tf32-rounded
__device__ float g_L [(size_t)Bn * Nn];        // row sums
__device__ float g_scl[Vd];
__device__ float g_shf[Vd];

// ===========================================================================
// Helpers (portable ISA: sm_80-class mma.sync + cp.async only)
// ===========================================================================
__device__ __forceinline__ uint32_t smem_u32(const void* p) {
    uint32_t a;
    asm("{ .reg .u64 t; cvta.to.shared.u64 t, %1; cvt.u32.u64 %0, t; }" : "=r"(a) : "l"(p));
    return a;
}
__device__ __forceinline__ uint32_t f2tf32(float x) {
    uint32_t u;
    asm("cvt.rna.tf32.f32 %0, %1;" : "=r"(u) : "f"(x));
    return u;
}
__device__ __forceinline__ float tf32r(float x) { return __uint_as_float(f2tf32(x)); }
__device__ __forceinline__ void cp_async16(uint32_t saddr, const void* gaddr) {
    asm volatile("cp.async.ca.shared.global [%0], [%1], 16;"
                 :: "r"(saddr), "l"(gaddr) : "memory");
}
__device__ __forceinline__ void cp_commit() {
    asm volatile("cp.async.commit_group;" ::: "memory");
}
__device__ __forceinline__ void cp_wait2() {
    asm volatile("cp.async.wait_group 2;" ::: "memory");
}
__device__ __forceinline__ void cp_wait1() {
    asm volatile("cp.async.wait_group 1;" ::: "memory");
}
__device__ __forceinline__ void cp_wait0() {
    asm volatile("cp.async.wait_group 0;" ::: "memory");
}
__device__ __forceinline__ void mma_tf32(float* d, const uint32_t* a, const uint32_t* b) {
    asm volatile(
        "mma.sync.aligned.m16n8k8.row.col.f32.tf32.tf32.f32 "
        "{%0,%1,%2,%3}, {%4,%5,%6,%7}, {%8,%9}, {%0,%1,%2,%3};"
        : "+f"(d[0]), "+f"(d[1]), "+f"(d[2]), "+f"(d[3])
        : "r"(a[0]), "r"(a[1]), "r"(a[2]), "r"(a[3]), "r"(b[0]), "r"(b[1]));
}
__device__ __forceinline__ void mma_bf16(float* d, const uint32_t* a, const uint32_t* b) {
    asm volatile(
        "mma.sync.aligned.m16n8k16.row.col.f32.bf16.bf16.f32 "
        "{%0,%1,%2,%3}, {%4,%5,%6,%7}, {%8,%9}, {%0,%1,%2,%3};"
        : "+f"(d[0]), "+f"(d[1]), "+f"(d[2]), "+f"(d[3])
        : "r"(a[0]), "r"(a[1]), "r"(a[2]), "r"(a[3]), "r"(b[0]), "r"(b[1]));
}
__device__ __forceinline__ uint32_t fu(float x) { return __float_as_uint(x); }
__device__ __forceinline__ uint32_t lds_u32(const char* p) { return *(const uint32_t*)p; }

// ===========================================================================
// BN scale/shift precompute
// ===========================================================================
__global__ void prep_kernel(const float* __restrict__ gamma, const float* __restrict__ beta,
                            const float* __restrict__ mean,  const float* __restrict__ var) {
    int i = threadIdx.x;
    if (i < Vd) {
        float s = gamma[i] * rsqrtf(var[i] + 1e-5f);
        g_scl[i] = s;
        g_shf[i] = beta[i] - mean[i] * s;
    }
}

// ===========================================================================
// Q/K projection (SIMT fp32, accurate) -> bf16 hi/lo split outputs
// ===========================================================================
__global__ __launch_bounds__(256) void qk_proj_kernel(
    const float* __restrict__ x, const float* __restrict__ W,
    const float* __restrict__ bias,
    __nv_bfloat16* __restrict__ out_hi, __nv_bfloat16* __restrict__ out_lo) {
    __shared__ float Xs[16][65];
    __shared__ float Ws[64][17];
    const int b  = blockIdx.z;
    const int n0 = blockIdx.x * 64;
    const int tid = threadIdx.x;
    const int tx = tid & 15, ty = tid >> 4;

    float acc[4][4] = {};
    const float* xb = x + (size_t)b * Cc * Nn;

    for (int c0 = 0; c0 < Cc; c0 += 16) {
        {
            int n_l = tid & 63, c_l = tid >> 6;
            #pragma unroll
            for (int it = 0; it < 4; it++)
                Xs[c_l + 4 * it][n_l] = xb[(size_t)(c0 + c_l + 4 * it) * Nn + n0 + n_l];
        }
        {
            int c_l = tid & 15, o_l = tid >> 4;
            #pragma unroll
            for (int it = 0; it < 4; it++)
                Ws[o_l + 16 * it][c_l] = W[(size_t)(o_l + 16 * it) * Cc + c0 + c_l];
        }
        __syncthreads();
        #pragma unroll
        for (int cc = 0; cc < 16; cc++) {
            float a[4], w[4];
            #pragma unroll
            for (int i = 0; i < 4; i++) a[i] = Xs[cc][ty + 16 * i];
            #pragma unroll
            for (int j = 0; j < 4; j++) w[j] = Ws[tx + 16 * j][cc];
            #pragma unroll
            for (int i = 0; i < 4; i++)
                #pragma unroll
                for (int j = 0; j < 4; j++)
                    acc[i][j] = fmaf(a[i], w[j], acc[i][j]);
        }
        __syncthreads();
    }

    #pragma unroll
    for (int i = 0; i < 4; i++) {
        int n = n0 + ty + 16 * i;
        #pragma unroll
        for (int j = 0; j < 4; j++) {
            int o = tx + 16 * j;
            float v  = acc[i][j] + bias[o];
            __nv_bfloat16 h = __float2bfloat16(v);
            __nv_bfloat16 l = __float2bfloat16(v - __bfloat162float(h));
            size_t idx = ((size_t)b * Nn + n) * Kd + o;
            out_hi[idx] = h;
            out_lo[idx] = l;
        }
    }
}

// ===========================================================================
// V projection on mma.sync tf32, 3-stage pipeline.
// Tile 128(n) x 128(o) x 32(c); 8 warps 2x4.
// SMEM floats: X stages @ {0,4352,8704} (32x136), W @ {13056,17664,22272} (128x36)
// ===========================================================================
static constexpr int V_NCH = Cc / 32;          // 16
static constexpr int V_FLOATS = 26880;         // 107.5 KB

__device__ __forceinline__ void vproj_stage(uint32_t sbase, int s,
                                            const float* xb, const float* W,
                                            int n0, int v0, int kc) {
    const int t = threadIdx.x;
    const uint32_t sX = sbase + (uint32_t)(s * 4352) * 4;
    const uint32_t sW = sbase + (uint32_t)(13056 + s * 4608) * 4;
    #pragma unroll
    for (int p = 0; p < 4; p++) {                 // X: 32 rows(c) x 32 f4
        int id = t + 256 * p, r = id >> 5, c4 = id & 31;
        cp_async16(sX + (uint32_t)(r * 136 + c4 * 4) * 4,
                   xb + (size_t)(kc * 32 + r) * Nn + n0 + c4 * 4);
    }
    #pragma unroll
    for (int p = 0; p < 4; p++) {                 // W: 128 rows(o) x 8 f4
        int id = t + 256 * p, r = id >> 3, c4 = id & 7;
        cp_async16(sW + (uint32_t)(r * 36 + c4 * 4) * 4,
                   W + (size_t)(v0 + r) * Cc + kc * 32 + c4 * 4);
    }
}

__global__ __launch_bounds__(256) void vproj_mma_kernel(const float* __restrict__ x,
                                                        const float* __restrict__ W) {
    extern __shared__ float sm[];
    const uint32_t sbase = smem_u32(sm);
    const int tid = threadIdx.x;
    const int wid = tid >> 5, lane = tid & 31;
    const int g = lane >> 2, c = lane & 3;
    const int wn = wid & 1, wv = wid >> 1;
    const int b  = blockIdx.z;
    const int n0 = blockIdx.y * 128;
    const int v0 = blockIdx.x * 128;
    const float* xb = x + (size_t)b * Cc * Nn;

    float acc[4][4][4] = {};

    vproj_stage(sbase, 0, xb, W, n0, v0, 0); cp_commit();
    vproj_stage(sbase, 1, xb, W, n0, v0, 1); cp_commit();

    for (int kc = 0; kc < V_NCH; kc++) {
        const int s = kc % 3;
        if (kc + 2 < V_NCH) {
            vproj_stage(sbase, (kc + 2) % 3, xb, W, n0, v0, kc + 2);
            cp_commit();
            cp_wait2();
        } else {
            cp_wait0();
        }
        __syncthreads();

        const float* Xs = sm + s * 4352;
        const float* Ws = sm + 13056 + s * 4608;

        #pragma unroll
        for (int ks = 0; ks < 4; ks++) {
            uint32_t af[4][4];
            #pragma unroll
            for (int i = 0; i < 4; i++) {
                const float* ap = Xs + (ks * 8 + c) * 136 + wn * 64 + i * 16 + g;
                af[i][0] = f2tf32(ap[0]);
                af[i][1] = f2tf32(ap[8]);
                af[i][2] = f2tf32(ap[4 * 136]);
                af[i][3] = f2tf32(ap[4 * 136 + 8]);
            }
            uint32_t bf[4][2];
            #pragma unroll
            for (int j = 0; j < 4; j++) {
                const float* bp = Ws + (wv * 32 + j * 8 + g) * 36 + ks * 8 + c;
                bf[j][0] = f2tf32(bp[0]);
                bf[j][1] = f2tf32(bp[4]);
            }
            #pragma unroll
            for (int i = 0; i < 4; i++)
                #pragma unroll
                for (int j = 0; j < 4; j++)
                    mma_tf32(acc[i][j], af[i], bf[j]);
        }
        __syncthreads();
    }

    #pragma unroll
    for (int j = 0; j < 4; j++) {
        const int o = v0 + wv * 32 + j * 8 + c * 2;
        const float s0 = g_scl[o],     h0 = g_shf[o];
        const float s1 = g_scl[o + 1], h1 = g_shf[o + 1];
        #pragma unroll
        for (int i = 0; i < 4; i++) {
            const int n = n0 + wn * 64 + i * 16 + g;
            float2 lo = { tf32r(fmaxf(fmaf(acc[i][j][0], s0, h0), 0.0f)),
                          tf32r(fmaxf(fmaf(acc[i][j][1], s1, h1), 0.0f)) };
            float2 hi = { tf32r(fmaxf(fmaf(acc[i][j][2], s0, h0), 0.0f)),
                          tf32r(fmaxf(fmaf(acc[i][j][3], s1, h1), 0.0f)) };
            *(float2*)&g_Vm[((size_t)b * Nn + n)     * Vd + o] = lo;
            *(float2*)&g_Vm[((size_t)b * Nn + n + 8) * Vd + o] = hi;
        }
    }
}

// ===========================================================================
// Energy on mma.sync BF16 with 3-term hi/lo split (fp32-accurate logits):
//   g_P[b][n][m] = tf32r(exp(q.k)), g_L[b][n] = sum_m
// Q resident (bf16 hi+lo), K double-buffered 64-row chunks.
// Row layout: 64 bf16 (128B) padded to 144B -> conflict-free frag loads.
// grid (Nn/128, Bn), block 256, warps 2(n) x 4(m).
// ===========================================================================
static constexpr int E_QH  = 0;                 // 128*144
static constexpr int E_QL  = 18432;
static constexpr int E_KH0 = 36864;             // 64*144 each
static constexpr int E_KH1 = 46080;
static constexpr int E_KL0 = 55296;
static constexpr int E_KL1 = 64512;
static constexpr int E_BYTES = 73728;

__global__ __launch_bounds__(256) void energy_mma_kernel() {
    extern __shared__ char smc[];
    __shared__ float sL[4][128];
    const uint32_t sbase = smem_u32(smc);
    const int tid = threadIdx.x;
    const int wid = tid >> 5, lane = tid & 31;
    const int g = lane >> 2, c = lane & 3;
    const int wn = wid & 1, wv = wid >> 1;
    const int b  = blockIdx.y;
    const int n0 = blockIdx.x * 128;

    const size_t qoff = ((size_t)b * Nn + n0) * Kd;
    const size_t koff = (size_t)b * Nn * Kd;

    // stage Q (hi+lo) + K chunk 0 -> group 0
    #pragma unroll
    for (int p = 0; p < 4; p++) {
        int id = tid + 256 * p, r = id >> 3, c8 = id & 7;
        cp_async16(sbase + E_QH + r * 144 + c8 * 16, g_Qh + qoff + (size_t)r * Kd + c8 * 8);
        cp_async16(sbase + E_QL + r * 144 + c8 * 16, g_Ql + qoff + (size_t)r * Kd + c8 * 8);
    }
    #pragma unroll
    for (int p = 0; p < 2; p++) {
        int id = tid + 256 * p, r = id >> 3, c8 = id & 7;
        cp_async16(sbase + E_KH0 + r * 144 + c8 * 16, g_Kh + koff + (size_t)r * Kd + c8 * 8);
        cp_async16(sbase + E_KL0 + r * 144 + c8 * 16, g_Kl + koff + (size_t)r * Kd + c8 * 8);
    }
    cp_commit();

    float rsum[4][2] = {};

    for (int mc = 0; mc < 64; mc++) {
        const int cur = mc & 1;
        if (mc + 1 < 64) {
            const uint32_t kh = sbase + ((mc + 1) & 1 ? E_KH1 : E_KH0);
            const uint32_t kl = sbase + ((mc + 1) & 1 ? E_KL1 : E_KL0);
            #pragma unroll
            for (int p = 0; p < 2; p++) {
                int id = tid + 256 * p, r = id >> 3, c8 = id & 7;
                cp_async16(kh + r * 144 + c8 * 16,
                           g_Kh + koff + (size_t)((mc + 1) * 64 + r) * Kd + c8 * 8);
                cp_async16(kl + r * 144 + c8 * 16,
                           g_Kl + koff + (size_t)((mc + 1) * 64 + r) * Kd + c8 * 8);
            }
            cp_commit();
            cp_wait1();
        } else {
            cp_wait0();
        }
        __syncthreads();

        const char* QH = smc + E_QH;
        const char* QL = smc + E_QL;
        const char* KH = smc + (cur ? E_KH1 : E_KH0);
        const char* KL = smc + (cur ? E_KL1 : E_KL0);

        float acc[4][2][4] = {};
        #pragma unroll
        for (int ks = 0; ks < 4; ks++) {          // 4 x k16 covers Kd=64
            uint32_t ah[4][4], al[4][4];
            #pragma unroll
            for (int i = 0; i < 4; i++) {
                const int off = (wn * 64 + i * 16 + g) * 144 + ks * 32 + c * 4;
                ah[i][0] = lds_u32(QH + off);
                ah[i][1] = lds_u32(QH + off + 8 * 144);
                ah[i][2] = lds_u32(QH + off + 16);
                ah[i][3] = lds_u32(QH + off + 8 * 144 + 16);
                al[i][0] = lds_u32(QL + off);
                al[i][1] = lds_u32(QL + off + 8 * 144);
                al[i][2] = lds_u32(QL + off + 16);
                al[i][3] = lds_u32(QL + off + 8 * 144 + 16);
            }
            uint32_t bh[2][2], bl[2][2];
            #pragma unroll
            for (int j = 0; j < 2; j++) {
                const int off = (wv * 16 + j * 8 + g) * 144 + ks * 32 + c * 4;
                bh[j][0] = lds_u32(KH + off);
                bh[j][1] = lds_u32(KH + off + 16);
                bl[j][0] = lds_u32(KL + off);
                bl[j][1] = lds_u32(KL + off + 16);
            }
            #pragma unroll
            for (int i = 0; i < 4; i++)
                #pragma unroll
                for (int j = 0; j < 2; j++) {
                    mma_bf16(acc[i][j], ah[i], bh[j]);
                    mma_bf16(acc[i][j], ah[i], bl[j]);
                    mma_bf16(acc[i][j], al[i], bh[j]);
                }
        }
        __syncthreads();

        #pragma unroll
        for (int i = 0; i < 4; i++) {
            const int r0 = n0 + wn * 64 + i * 16 + g;
            #pragma unroll
            for (int j = 0; j < 2; j++) {
                const int m = mc * 64 + wv * 16 + j * 8 + c * 2;
                float e00 = tf32r(__expf(acc[i][j][0]));
                float e01 = tf32r(__expf(acc[i][j][1]));
                float e10 = tf32r(__expf(acc[i][j][2]));
                float e11 = tf32r(__expf(acc[i][j][3]));
                *(float2*)&g_P[((size_t)b * Nn + r0)     * Nn + m] = make_float2(e00, e01);
                *(float2*)&g_P[((size_t)b * Nn + r0 + 8) * Nn + m] = make_float2(e10, e11);
                rsum[i][0] += e00 + e01;
                rsum[i][1] += e10 + e11;
            }
        }
    }

    #pragma unroll
    for (int i = 0; i < 4; i++)
        #pragma unroll
        for (int r = 0; r < 2; r++) {
            float v = rsum[i][r];
            v += __shfl_xor_sync(0xffffffffu, v, 1);
            v += __shfl_xor_sync(0xffffffffu, v, 2);
            rsum[i][r] = v;
        }
    if (c == 0) {
        #pragma unroll
        for (int i = 0; i < 4; i++) {
            sL[wv][wn * 64 + i * 16 + g]     = rsum[i][0];
            sL[wv][wn * 64 + i * 16 + g + 8] = rsum[i][1];
        }
    }
    __syncthreads();
    if (tid < 128)
        g_L[(size_t)b * Nn + n0 + tid] = sL[0][tid] + sL[1][tid] + sL[2][tid] + sL[3][tid];
}

// ===========================================================================
// PV GEMM (mma.sync tf32, pre-rounded operands), 3-stage pipeline:
//   out[b][v][n] = (1/L[n]) * sum_m P[n][m] Vm[m][v]
// Tile 128(n) x 128(v) x 64(m); warps 2x4.
// SMEM floats: A stages @ s*8704 (128x68), B @ 26112 + s*8704 (64x136)
// ===========================================================================
static constexpr int A_NCH = Nn / 64;           // 64
static constexpr int A_FLOATS = 52224;          // 208.9 KB

__device__ __forceinline__ void av_stage(uint32_t sbase, int s,
                                         const float* pA, const float* pB, int it) {
    const int t = threadIdx.x;
    const uint32_t sA = sbase + (uint32_t)(s * 8704) * 4;
    const uint32_t sB = sbase + (uint32_t)(26112 + s * 8704) * 4;
    #pragma unroll
    for (int p = 0; p < 8; p++) {                 // A: 128 rows(n) x 16 f4
        int id = t + 256 * p, r = id >> 4, c4 = id & 15;
        cp_async16(sA + (uint32_t)(r * 68 + c4 * 4) * 4,
                   pA + (size_t)r * Nn + it * 64 + c4 * 4);
    }
    #pragma unroll
    for (int p = 0; p < 8; p++) {                 // B: 64 rows(m) x 32 f4
        int id = t + 256 * p, r = id >> 5, c4 = id & 31;
        cp_async16(sB + (uint32_t)(r * 136 + c4 * 4) * 4,
                   pB + (size_t)(it * 64 + r) * Vd + c4 * 4);
    }
}

__global__ __launch_bounds__(256) void av_mma_kernel(float* __restrict__ out) {
    extern __shared__ float sm[];
    const uint32_t sbase = smem_u32(sm);
    const int tid  = threadIdx.x;
    const int wid  = tid >> 5, lane = tid & 31;
    const int g = lane >> 2, c = lane & 3;
    const int wn = wid & 1, wv = wid >> 1;
    const int b  = blockIdx.z;
    const int n0 = blockIdx.y * 128;
    const int v0 = blockIdx.x * 128;

    const float* pA = g_P  + ((size_t)b * Nn + n0) * Nn;
    const float* pB = g_Vm + ((size_t)b * Nn) * Vd + v0;

    float acc[4][4][4] = {};

    av_stage(sbase, 0, pA, pB, 0); cp_commit();
    av_stage(sbase, 1, pA, pB, 1); cp_commit();

    for (int it = 0; it < A_NCH; it++) {
        const int s = it % 3;
        if (it + 2 < A_NCH) {
            av_stage(sbase, (it + 2) % 3, pA, pB, it + 2);
            cp_commit();
            cp_wait2();
        } else {
            cp_wait0();
        }
        __syncthreads();

        const float* As = sm + s * 8704;
        const float* Bs = sm + 26112 + s * 8704;

        #pragma unroll
        for (int ks = 0; ks < 8; ks++) {
            uint32_t af[4][4];
            #pragma unroll
            for (int i = 0; i < 4; i++) {
                const float* ap = As + (wn * 64 + i * 16 + g) * 68 + ks * 8 + c;
                af[i][0] = fu(ap[0]);
                af[i][1] = fu(ap[8 * 68]);
                af[i][2] = fu(ap[4]);
                af[i][3] = fu(ap[8 * 68 + 4]);
            }
            uint32_t bf[4][2];
            #pragma unroll
            for (int j = 0; j < 4; j++) {
                const float* bp = Bs + (ks * 8 + c) * 136 + wv * 32 + j * 8 + g;
                bf[j][0] = fu(bp[0]);
                bf[j][1] = fu(bp[4 * 136]);
            }
            #pragma unroll
            for (int i = 0; i < 4; i++)
                #pragma unroll
                for (int j = 0; j < 4; j++)
                    mma_tf32(acc[i][j], af[i], bf[j]);
        }
        __syncthreads();
    }

    #pragma unroll
    for (int i = 0; i < 4; i++) {
        const int n_lo = n0 + wn * 64 + i * 16 + g;
        const float linv_lo = 1.0f / g_L[(size_t)b * Nn + n_lo];
        const float linv_hi = 1.0f / g_L[(size_t)b * Nn + n_lo + 8];
        #pragma unroll
        for (int j = 0; j < 4; j++) {
            const int v = v0 + wv * 32 + j * 8 + c * 2;
            float* o0p = out + ((size_t)b * Vd + v)     * Nn + n_lo;
            float* o1p = out + ((size_t)b * Vd + v + 1) * Nn + n_lo;
            o0p[0] = acc[i][j][0] * linv_lo;
            o1p[0] = acc[i][j][1] * linv_lo;
            o0p[8] = acc[i][j][2] * linv_hi;
            o1p[8] = acc[i][j][3] * linv_hi;
        }
    }
}

// ===========================================================================
extern "C" void kernel_launch(void* const* d_in, const int* in_sizes, int n_in,
                              void* d_out, int out_size) {
    const float* x     = (const float*)d_in[0];
    const float* Wq    = (const float*)d_in[1];
    const float* bq    = (const float*)d_in[2];
    const float* Wk    = (const float*)d_in[3];
    const float* bk    = (const float*)d_in[4];
    const float* Wv    = (const float*)d_in[5];
    const float* gamma = (const float*)d_in[6];
    const float* beta  = (const float*)d_in[7];
    const float* mean  = (const float*)d_in[8];
    const float* var   = (const float*)d_in[9];
    float* out = (float*)d_out;

    __nv_bfloat16 *Qhp, *Qlp, *Khp, *Klp;
    cudaGetSymbolAddress((void**)&Qhp, g_Qh);
    cudaGetSymbolAddress((void**)&Qlp, g_Ql);
    cudaGetSymbolAddress((void**)&Khp, g_Kh);
    cudaGetSymbolAddress((void**)&Klp, g_Kl);

    static int smem_set = 0;
    if (!smem_set) {
        cudaFuncSetAttribute(vproj_mma_kernel,
                             cudaFuncAttributeMaxDynamicSharedMemorySize, V_FLOATS * 4);
        cudaFuncSetAttribute(energy_mma_kernel,
                             cudaFuncAttributeMaxDynamicSharedMemorySize, E_BYTES);
        cudaFuncSetAttribute(av_mma_kernel,
                             cudaFuncAttributeMaxDynamicSharedMemorySize, A_FLOATS * 4);
        smem_set = 1;
    }

    prep_kernel<<<1, 512>>>(gamma, beta, mean, var);

    qk_proj_kernel<<<dim3(Nn / 64, 1, Bn), 256>>>(x, Wq, bq, Qhp, Qlp);
    qk_proj_kernel<<<dim3(Nn / 64, 1, Bn), 256>>>(x, Wk, bk, Khp, Klp);
    vproj_mma_kernel<<<dim3(Vd / 128, Nn / 128, Bn), 256, V_FLOATS * 4>>>(x, Wv);

    energy_mma_kernel<<<dim3(Nn / 128, Bn), 256, E_BYTES>>>();

    av_mma_kernel<<<dim3(Vd / 128, Nn / 128, Bn), 256, A_FLOATS * 4>>>(out);
}

// round 6
// speedup vs baseline: 1.1703x; 1.1703x over previous
#include <cuda_runtime.h>
#include <cuda_bf16.h>
#include <cstdint>
#include <cstddef>

static constexpr int Bn = 8;
static constexpr int Cc = 512;
static constexpr int Nn = 4096;   // H*W
static constexpr int Kd = 64;
static constexpr int Vd = 512;

// Scratch (device globals)
__device__ __nv_bfloat16 g_Qh[(size_t)Bn * Nn * Kd];   // [b][n][k] bf16 hi
__device__ __nv_bfloat16 g_Ql[(size_t)Bn * Nn * Kd];   // bf16 residual lo
__device__ __nv_bfloat16 g_Kh[(size_t)Bn * Nn * Kd];
__device__ __nv_bfloat16 g_Kl[(size_t)Bn * Nn * Kd];
// V in packed B-pair layout: [b][mt 0..63][ks 0..7][v 0..511][cpair 0..3][half 0..1]
__device__ float g_Vb[(size_t)Bn * 64 * 32768];
// P = exp(energy) in packed A-fragment tiles:
// [b][nt 0..31][mt 0..63][ (i_blk*8+ks)*128 + lane*4 + q ]   (8192 floats / tile)
__device__ float g_P [(size_t)Bn * 32 * 64 * 8192];
__device__ float g_L [(size_t)Bn * Nn];        // row sums
__device__ float g_scl[Vd];
__device__ float g_shf[Vd];

// ===========================================================================
// Helpers (portable ISA: sm_80-class mma.sync + cp.async only)
// ===========================================================================
__device__ __forceinline__ uint32_t smem_u32(const void* p) {
    uint32_t a;
    asm("{ .reg .u64 t; cvta.to.shared.u64 t, %1; cvt.u32.u64 %0, t; }" : "=r"(a) : "l"(p));
    return a;
}
__device__ __forceinline__ uint32_t f2tf32(float x) {
    uint32_t u;
    asm("cvt.rna.tf32.f32 %0, %1;" : "=r"(u) : "f"(x));
    return u;
}
__device__ __forceinline__ float tf32r(float x) { return __uint_as_float(f2tf32(x)); }
__device__ __forceinline__ void cp_async16(uint32_t saddr, const void* gaddr) {
    asm volatile("cp.async.ca.shared.global [%0], [%1], 16;"
                 :: "r"(saddr), "l"(gaddr) : "memory");
}
__device__ __forceinline__ void cp_commit() {
    asm volatile("cp.async.commit_group;" ::: "memory");
}
__device__ __forceinline__ void cp_wait1() {
    asm volatile("cp.async.wait_group 1;" ::: "memory");
}
__device__ __forceinline__ void cp_wait0() {
    asm volatile("cp.async.wait_group 0;" ::: "memory");
}
__device__ __forceinline__ void mma_tf32(float* d, const uint32_t* a, const uint32_t* b) {
    asm volatile(
        "mma.sync.aligned.m16n8k8.row.col.f32.tf32.tf32.f32 "
        "{%0,%1,%2,%3}, {%4,%5,%6,%7}, {%8,%9}, {%0,%1,%2,%3};"
        : "+f"(d[0]), "+f"(d[1]), "+f"(d[2]), "+f"(d[3])
        : "r"(a[0]), "r"(a[1]), "r"(a[2]), "r"(a[3]), "r"(b[0]), "r"(b[1]));
}
__device__ __forceinline__ void mma_bf16(float* d, const uint32_t* a, const uint32_t* b) {
    asm volatile(
        "mma.sync.aligned.m16n8k16.row.col.f32.bf16.bf16.f32 "
        "{%0,%1,%2,%3}, {%4,%5,%6,%7}, {%8,%9}, {%0,%1,%2,%3};"
        : "+f"(d[0]), "+f"(d[1]), "+f"(d[2]), "+f"(d[3])
        : "r"(a[0]), "r"(a[1]), "r"(a[2]), "r"(a[3]), "r"(b[0]), "r"(b[1]));
}
__device__ __forceinline__ uint32_t fu(float x) { return __float_as_uint(x); }
__device__ __forceinline__ uint32_t lds_u32(const char* p) { return *(const uint32_t*)p; }

// ===========================================================================
// BN scale/shift precompute
// ===========================================================================
__global__ void prep_kernel(const float* __restrict__ gamma, const float* __restrict__ beta,
                            const float* __restrict__ mean,  const float* __restrict__ var) {
    int i = threadIdx.x;
    if (i < Vd) {
        float s = gamma[i] * rsqrtf(var[i] + 1e-5f);
        g_scl[i] = s;
        g_shf[i] = beta[i] - mean[i] * s;
    }
}

// ===========================================================================
// Q+K projection merged (SIMT fp32, accurate) -> bf16 hi/lo split outputs
// grid (Nn/64, 2, Bn): blockIdx.y = 0 -> Q, 1 -> K
// ===========================================================================
__global__ __launch_bounds__(256) void qk_proj_kernel(
    const float* __restrict__ x,
    const float* __restrict__ Wq, const float* __restrict__ bq,
    const float* __restrict__ Wk, const float* __restrict__ bk) {
    __shared__ float Xs[16][65];
    __shared__ float Ws[64][17];
    const int which = blockIdx.y;
    const float* W    = which ? Wk : Wq;
    const float* bias = which ? bk : bq;
    __nv_bfloat16* out_hi = which ? g_Kh : g_Qh;
    __nv_bfloat16* out_lo = which ? g_Kl : g_Ql;

    const int b  = blockIdx.z;
    const int n0 = blockIdx.x * 64;
    const int tid = threadIdx.x;
    const int tx = tid & 15, ty = tid >> 4;

    float acc[4][4] = {};
    const float* xb = x + (size_t)b * Cc * Nn;

    for (int c0 = 0; c0 < Cc; c0 += 16) {
        {
            int n_l = tid & 63, c_l = tid >> 6;
            #pragma unroll
            for (int it = 0; it < 4; it++)
                Xs[c_l + 4 * it][n_l] = xb[(size_t)(c0 + c_l + 4 * it) * Nn + n0 + n_l];
        }
        {
            int c_l = tid & 15, o_l = tid >> 4;
            #pragma unroll
            for (int it = 0; it < 4; it++)
                Ws[o_l + 16 * it][c_l] = W[(size_t)(o_l + 16 * it) * Cc + c0 + c_l];
        }
        __syncthreads();
        #pragma unroll
        for (int cc = 0; cc < 16; cc++) {
            float a[4], w[4];
            #pragma unroll
            for (int i = 0; i < 4; i++) a[i] = Xs[cc][ty + 16 * i];
            #pragma unroll
            for (int j = 0; j < 4; j++) w[j] = Ws[tx + 16 * j][cc];
            #pragma unroll
            for (int i = 0; i < 4; i++)
                #pragma unroll
                for (int j = 0; j < 4; j++)
                    acc[i][j] = fmaf(a[i], w[j], acc[i][j]);
        }
        __syncthreads();
    }

    #pragma unroll
    for (int i = 0; i < 4; i++) {
        int n = n0 + ty + 16 * i;
        #pragma unroll
        for (int j = 0; j < 4; j++) {
            int o = tx + 16 * j;
            float v  = acc[i][j] + bias[o];
            __nv_bfloat16 h = __float2bfloat16(v);
            __nv_bfloat16 l = __float2bfloat16(v - __bfloat162float(h));
            size_t idx = ((size_t)b * Nn + n) * Kd + o;
            out_hi[idx] = h;
            out_lo[idx] = l;
        }
    }
}

// ===========================================================================
// V projection on mma.sync tf32 (R4 2-stage), epilogue -> packed g_Vb.
// Tile 128(n=m) x 128(o=v) x 32(c); 8 warps 2x4.
// ===========================================================================
static constexpr int V_OFX0 = 0;               // 32*136 = 4352 floats
static constexpr int V_OFX1 = 4352;
static constexpr int V_OFW0 = 8704;            // 128*36 = 4608 floats
static constexpr int V_OFW1 = 13312;
static constexpr int V_FLOATS = 17920;         // 71.7 KB

__device__ __forceinline__ void vproj_stage(uint32_t sbase, int buf,
                                            const float* xb, const float* W,
                                            int n0, int v0, int kc) {
    const int t = threadIdx.x;
    const uint32_t sX = sbase + (buf ? V_OFX1 : V_OFX0) * 4;
    const uint32_t sW = sbase + (buf ? V_OFW1 : V_OFW0) * 4;
    #pragma unroll
    for (int p = 0; p < 4; p++) {                 // X: 32 rows(c) x 32 f4
        int id = t + 256 * p, r = id >> 5, c4 = id & 31;
        cp_async16(sX + (uint32_t)(r * 136 + c4 * 4) * 4,
                   xb + (size_t)(kc * 32 + r) * Nn + n0 + c4 * 4);
    }
    #pragma unroll
    for (int p = 0; p < 4; p++) {                 // W: 128 rows(o) x 8 f4
        int id = t + 256 * p, r = id >> 3, c4 = id & 7;
        cp_async16(sW + (uint32_t)(r * 36 + c4 * 4) * 4,
                   W + (size_t)(v0 + r) * Cc + kc * 32 + c4 * 4);
    }
}

__global__ __launch_bounds__(256) void vproj_mma_kernel(const float* __restrict__ x,
                                                        const float* __restrict__ W) {
    extern __shared__ float sm[];
    const uint32_t sbase = smem_u32(sm);
    const int tid = threadIdx.x;
    const int wid = tid >> 5, lane = tid & 31;
    const int g = lane >> 2, c = lane & 3;
    const int wn = wid & 1, wv = wid >> 1;
    const int b  = blockIdx.z;
    const int n0 = blockIdx.y * 128;
    const int v0 = blockIdx.x * 128;
    const float* xb = x + (size_t)b * Cc * Nn;

    float acc[4][4][4] = {};

    vproj_stage(sbase, 0, xb, W, n0, v0, 0);
    cp_commit();

    for (int kc = 0; kc < Cc / 32; kc++) {
        const int cur = kc & 1;
        if (kc + 1 < Cc / 32) {
            vproj_stage(sbase, cur ^ 1, xb, W, n0, v0, kc + 1);
            cp_commit();
            cp_wait1();
        } else {
            cp_wait0();
        }
        __syncthreads();

        const float* Xs = sm + (cur ? V_OFX1 : V_OFX0);
        const float* Ws = sm + (cur ? V_OFW1 : V_OFW0);

        #pragma unroll
        for (int ks = 0; ks < 4; ks++) {
            uint32_t af[4][4];
            #pragma unroll
            for (int i = 0; i < 4; i++) {
                const float* ap = Xs + (ks * 8 + c) * 136 + wn * 64 + i * 16 + g;
                af[i][0] = f2tf32(ap[0]);
                af[i][1] = f2tf32(ap[8]);
                af[i][2] = f2tf32(ap[4 * 136]);
                af[i][3] = f2tf32(ap[4 * 136 + 8]);
            }
            uint32_t bf[4][2];
            #pragma unroll
            for (int j = 0; j < 4; j++) {
                const float* bp = Ws + (wv * 32 + j * 8 + g) * 36 + ks * 8 + c;
                bf[j][0] = f2tf32(bp[0]);
                bf[j][1] = f2tf32(bp[4]);
            }
            #pragma unroll
            for (int i = 0; i < 4; i++)
                #pragma unroll
                for (int j = 0; j < 4; j++)
                    mma_tf32(acc[i][j], af[i], bf[j]);
        }
        __syncthreads();
    }

    // Epilogue: BN+ReLU, tf32-round, write packed B-pair layout g_Vb.
    // m = n0 + wn*64 + i*16 + g (+8), v = v0 + wv*32 + j*8 + 2c (+1)
    #pragma unroll
    for (int j = 0; j < 4; j++) {
        const int vv = v0 + wv * 32 + j * 8 + 2 * c;
        const float s0 = g_scl[vv],     h0 = g_shf[vv];
        const float s1 = g_scl[vv + 1], h1 = g_shf[vv + 1];
        #pragma unroll
        for (int i = 0; i < 4; i++) {
            const int mt = blockIdx.y * 2 + wn;     // (n0 + wn*64 + i*16)>>6
            const int ks0 = i * 2;
            float e00 = tf32r(fmaxf(fmaf(acc[i][j][0], s0, h0), 0.0f));
            float e01 = tf32r(fmaxf(fmaf(acc[i][j][1], s1, h1), 0.0f));
            float e10 = tf32r(fmaxf(fmaf(acc[i][j][2], s0, h0), 0.0f));
            float e11 = tf32r(fmaxf(fmaf(acc[i][j][3], s1, h1), 0.0f));
            size_t a0 = ((size_t)b * 64 + mt) * 32768 + (size_t)ks0 * 4096
                      + (size_t)vv * 8 + (g & 3) * 2 + (g >> 2);
            g_Vb[a0]            = e00;
            g_Vb[a0 + 8]        = e01;
            g_Vb[a0 + 4096]     = e10;
            g_Vb[a0 + 4096 + 8] = e11;
        }
    }
}

// ===========================================================================
// Energy on mma.sync BF16, 3-term hi/lo split; epilogue writes packed
// A-fragment tiles of g_P (+ row sums g_L).
// grid (Nn/128, Bn), block 256, warps 2(n) x 4(m).
// ===========================================================================
static constexpr int E_QH  = 0;                 // 128*144
static constexpr int E_QL  = 18432;
static constexpr int E_KH0 = 36864;             // 64*144 each
static constexpr int E_KH1 = 46080;
static constexpr int E_KL0 = 55296;
static constexpr int E_KL1 = 64512;
static constexpr int E_BYTES = 73728;

__global__ __launch_bounds__(256) void energy_mma_kernel() {
    extern __shared__ char smc[];
    __shared__ float sL[4][128];
    const uint32_t sbase = smem_u32(smc);
    const int tid = threadIdx.x;
    const int wid = tid >> 5, lane = tid & 31;
    const int g = lane >> 2, c = lane & 3;
    const int wn = wid & 1, wv = wid >> 1;
    const int b  = blockIdx.y;
    const int nt = blockIdx.x;
    const int n0 = nt * 128;

    const size_t qoff = ((size_t)b * Nn + n0) * Kd;
    const size_t koff = (size_t)b * Nn * Kd;

    #pragma unroll
    for (int p = 0; p < 4; p++) {
        int id = tid + 256 * p, r = id >> 3, c8 = id & 7;
        cp_async16(sbase + E_QH + r * 144 + c8 * 16, g_Qh + qoff + (size_t)r * Kd + c8 * 8);
        cp_async16(sbase + E_QL + r * 144 + c8 * 16, g_Ql + qoff + (size_t)r * Kd + c8 * 8);
    }
    #pragma unroll
    for (int p = 0; p < 2; p++) {
        int id = tid + 256 * p, r = id >> 3, c8 = id & 7;
        cp_async16(sbase + E_KH0 + r * 144 + c8 * 16, g_Kh + koff + (size_t)r * Kd + c8 * 8);
        cp_async16(sbase + E_KL0 + r * 144 + c8 * 16, g_Kl + koff + (size_t)r * Kd + c8 * 8);
    }
    cp_commit();

    float rsum[4][2] = {};

    for (int mc = 0; mc < 64; mc++) {
        const int cur = mc & 1;
        if (mc + 1 < 64) {
            const uint32_t kh = sbase + ((mc + 1) & 1 ? E_KH1 : E_KH0);
            const uint32_t kl = sbase + ((mc + 1) & 1 ? E_KL1 : E_KL0);
            #pragma unroll
            for (int p = 0; p < 2; p++) {
                int id = tid + 256 * p, r = id >> 3, c8 = id & 7;
                cp_async16(kh + r * 144 + c8 * 16,
                           g_Kh + koff + (size_t)((mc + 1) * 64 + r) * Kd + c8 * 8);
                cp_async16(kl + r * 144 + c8 * 16,
                           g_Kl + koff + (size_t)((mc + 1) * 64 + r) * Kd + c8 * 8);
            }
            cp_commit();
            cp_wait1();
        } else {
            cp_wait0();
        }
        __syncthreads();

        const char* QH = smc + E_QH;
        const char* QL = smc + E_QL;
        const char* KH = smc + (cur ? E_KH1 : E_KH0);
        const char* KL = smc + (cur ? E_KL1 : E_KL0);

        float acc[4][2][4] = {};
        #pragma unroll
        for (int ks = 0; ks < 4; ks++) {          // 4 x k16 covers Kd=64
            uint32_t ah[4][4], al[4][4];
            #pragma unroll
            for (int i = 0; i < 4; i++) {
                const int off = (wn * 64 + i * 16 + g) * 144 + ks * 32 + c * 4;
                ah[i][0] = lds_u32(QH + off);
                ah[i][1] = lds_u32(QH + off + 8 * 144);
                ah[i][2] = lds_u32(QH + off + 16);
                ah[i][3] = lds_u32(QH + off + 8 * 144 + 16);
                al[i][0] = lds_u32(QL + off);
                al[i][1] = lds_u32(QL + off + 8 * 144);
                al[i][2] = lds_u32(QL + off + 16);
                al[i][3] = lds_u32(QL + off + 8 * 144 + 16);
            }
            uint32_t bh[2][2], bl[2][2];
            #pragma unroll
            for (int j = 0; j < 2; j++) {
                const int off = (wv * 16 + j * 8 + g) * 144 + ks * 32 + c * 4;
                bh[j][0] = lds_u32(KH + off);
                bh[j][1] = lds_u32(KH + off + 16);
                bl[j][0] = lds_u32(KL + off);
                bl[j][1] = lds_u32(KL + off + 16);
            }
            #pragma unroll
            for (int i = 0; i < 4; i++)
                #pragma unroll
                for (int j = 0; j < 2; j++) {
                    mma_bf16(acc[i][j], ah[i], bh[j]);
                    mma_bf16(acc[i][j], ah[i], bl[j]);
                    mma_bf16(acc[i][j], al[i], bh[j]);
                }
        }
        __syncthreads();

        // Epilogue: exp, tf32-round, write packed A-fragment tile.
        const size_t tile0 = (((size_t)b * 32 + nt) * 64 + mc) * 8192;
        #pragma unroll
        for (int i = 0; i < 4; i++) {
            const int i_blk = wn * 4 + i;
            #pragma unroll
            for (int j = 0; j < 2; j++) {
                const int ks = wv * 2 + j;
                float e00 = tf32r(__expf(acc[i][j][0]));
                float e01 = tf32r(__expf(acc[i][j][1]));
                float e10 = tf32r(__expf(acc[i][j][2]));
                float e11 = tf32r(__expf(acc[i][j][3]));
                size_t off = tile0 + (size_t)((i_blk * 8 + ks) * 128
                           + (g * 4 + (c & 1) * 2) * 4 + (c >> 1) * 2);
                *(float2*)&g_P[off]     = make_float2(e00, e10);
                *(float2*)&g_P[off + 4] = make_float2(e01, e11);
                rsum[i][0] += e00 + e01;
                rsum[i][1] += e10 + e11;
            }
        }
    }

    #pragma unroll
    for (int i = 0; i < 4; i++)
        #pragma unroll
        for (int r = 0; r < 2; r++) {
            float v = rsum[i][r];
            v += __shfl_xor_sync(0xffffffffu, v, 1);
            v += __shfl_xor_sync(0xffffffffu, v, 2);
            rsum[i][r] = v;
        }
    if (c == 0) {
        #pragma unroll
        for (int i = 0; i < 4; i++) {
            sL[wv][wn * 64 + i * 16 + g]     = rsum[i][0];
            sL[wv][wn * 64 + i * 16 + g + 8] = rsum[i][1];
        }
    }
    __syncthreads();
    if (tid < 128)
        g_L[(size_t)b * Nn + n0 + tid] = sL[0][tid] + sL[1][tid] + sL[2][tid] + sL[3][tid];
}

// ===========================================================================
// PV GEMM (mma.sync tf32, packed operands, no cvt, conflict-free LDS.128/64):
//   out[b][v][n] = (1/L[n]) * sum_m P[n][m] Vb[m][v]
// Block 128(n) x 256(v), warp tile 64x64 (warps 2x4), K-chunk 64, 2-stage.
// SMEM: A stages @ {0, 8192} floats (32KB each),
//       B stages @ {16384, 32768} floats (64KB each). Total 192KB.
// ===========================================================================
static constexpr int A_SM_B0 = 16384;
static constexpr int A_BYTES = 196608;

__device__ __forceinline__ void av_stage(uint32_t sbase, int buf,
                                         const float* gA, const float* gB, int it) {
    const int t = threadIdx.x;
    const uint32_t sA = sbase + (buf ? 8192u : 0u) * 4;
    const uint32_t sB = sbase + (A_SM_B0 + buf * 16384u) * 4;
    const float* gAt = gA + (size_t)it * 8192;
    const float* gBt = gB + (size_t)it * 32768;
    #pragma unroll
    for (int p = 0; p < 8; p++) {                 // A tile: 8192 floats linear
        int id = t + 256 * p;
        cp_async16(sA + (uint32_t)id * 16, gAt + id * 4);
    }
    #pragma unroll
    for (int p = 0; p < 16; p++) {                // B tile: 8 ks-blocks x 2048 floats
        int id = t + 256 * p, ks = id >> 9, w = id & 511;
        cp_async16(sB + (uint32_t)(ks * 2048 + w * 4) * 4,
                   gBt + (size_t)ks * 4096 + w * 4);
    }
}

__global__ __launch_bounds__(256) void av_mma_kernel(float* __restrict__ out) {
    extern __shared__ float sm[];
    const uint32_t sbase = smem_u32(sm);
    const int tid  = threadIdx.x;
    const int wid  = tid >> 5, lane = tid & 31;
    const int g = lane >> 2, c = lane & 3;
    const int wn = wid & 1, wv = wid >> 1;
    const int b  = blockIdx.z;
    const int nt = blockIdx.y;
    const int n0 = nt * 128;
    const int v0 = blockIdx.x * 256;

    const float* gA = g_P  + (((size_t)b * 32 + nt) * 64) * 8192;
    const float* gB = g_Vb + ((size_t)b * 64) * 32768 + (size_t)v0 * 8;

    float acc[4][8][4] = {};

    av_stage(sbase, 0, gA, gB, 0);
    cp_commit();

    for (int it = 0; it < 64; it++) {
        const int cur = it & 1;
        if (it + 1 < 64) {
            av_stage(sbase, cur ^ 1, gA, gB, it + 1);
            cp_commit();
            cp_wait1();
        } else {
            cp_wait0();
        }
        __syncthreads();

        const float* As = sm + cur * 8192;
        const float* Bs = sm + A_SM_B0 + cur * 16384;

        #pragma unroll
        for (int ks = 0; ks < 8; ks++) {
            uint32_t af[4][4];
            #pragma unroll
            for (int i = 0; i < 4; i++) {
                float4 v4 = *(const float4*)(As + ((wn * 4 + i) * 8 + ks) * 128 + lane * 4);
                af[i][0] = fu(v4.x); af[i][1] = fu(v4.y);
                af[i][2] = fu(v4.z); af[i][3] = fu(v4.w);
            }
            uint32_t bf[8][2];
            #pragma unroll
            for (int j = 0; j < 8; j++) {
                float2 v2 = *(const float2*)(Bs + ks * 2048 + (wv * 64 + j * 8 + g) * 8 + c * 2);
                bf[j][0] = fu(v2.x); bf[j][1] = fu(v2.y);
            }
            #pragma unroll
            for (int i = 0; i < 4; i++)
                #pragma unroll
                for (int j = 0; j < 8; j++)
                    mma_tf32(acc[i][j], af[i], bf[j]);
        }
        __syncthreads();
    }

    #pragma unroll
    for (int i = 0; i < 4; i++) {
        const int n_lo = n0 + wn * 64 + i * 16 + g;
        const float linv_lo = 1.0f / g_L[(size_t)b * Nn + n_lo];
        const float linv_hi = 1.0f / g_L[(size_t)b * Nn + n_lo + 8];
        #pragma unroll
        for (int j = 0; j < 8; j++) {
            const int v = v0 + wv * 64 + j * 8 + c * 2;
            float* o0p = out + ((size_t)b * Vd + v)     * Nn + n_lo;
            float* o1p = out + ((size_t)b * Vd + v + 1) * Nn + n_lo;
            o0p[0] = acc[i][j][0] * linv_lo;
            o1p[0] = acc[i][j][1] * linv_lo;
            o0p[8] = acc[i][j][2] * linv_hi;
            o1p[8] = acc[i][j][3] * linv_hi;
        }
    }
}

// ===========================================================================
extern "C" void kernel_launch(void* const* d_in, const int* in_sizes, int n_in,
                              void* d_out, int out_size) {
    const float* x     = (const float*)d_in[0];
    const float* Wq    = (const float*)d_in[1];
    const float* bq    = (const float*)d_in[2];
    const float* Wk    = (const float*)d_in[3];
    const float* bk    = (const float*)d_in[4];
    const float* Wv    = (const float*)d_in[5];
    const float* gamma = (const float*)d_in[6];
    const float* beta  = (const float*)d_in[7];
    const float* mean  = (const float*)d_in[8];
    const float* var   = (const float*)d_in[9];
    float* out = (float*)d_out;

    static int smem_set = 0;
    if (!smem_set) {
        cudaFuncSetAttribute(vproj_mma_kernel,
                             cudaFuncAttributeMaxDynamicSharedMemorySize, V_FLOATS * 4);
        cudaFuncSetAttribute(energy_mma_kernel,
                             cudaFuncAttributeMaxDynamicSharedMemorySize, E_BYTES);
        cudaFuncSetAttribute(av_mma_kernel,
                             cudaFuncAttributeMaxDynamicSharedMemorySize, A_BYTES);
        smem_set = 1;
    }

    prep_kernel<<<1, 512>>>(gamma, beta, mean, var);

    qk_proj_kernel<<<dim3(Nn / 64, 2, Bn), 256>>>(x, Wq, bq, Wk, bk);
    vproj_mma_kernel<<<dim3(Vd / 128, Nn / 128, Bn), 256, V_FLOATS * 4>>>(x, Wv);

    energy_mma_kernel<<<dim3(Nn / 128, Bn), 256, E_BYTES>>>();

    av_mma_kernel<<<dim3(Vd / 256, Nn / 128, Bn), 256, A_BYTES>>>(out);
}

// round 8
// speedup vs baseline: 1.3264x; 1.1334x over previous
#include <cuda_runtime.h>
#include <cuda_bf16.h>
#include <cstdint>
#include <cstddef>

static constexpr int Bn = 8;
static constexpr int Cc = 512;
static constexpr int Nn = 4096;   // H*W
static constexpr int Kd = 64;
static constexpr int Vd = 512;

// Scratch (device globals)
__device__ __nv_bfloat16 g_Qh[(size_t)Bn * Nn * Kd];   // [b][n][k] bf16 hi
__device__ __nv_bfloat16 g_Ql[(size_t)Bn * Nn * Kd];   // bf16 residual lo
__device__ __nv_bfloat16 g_Kh[(size_t)Bn * Nn * Kd];
__device__ __nv_bfloat16 g_Kl[(size_t)Bn * Nn * Kd];
// V in packed B-pair layout: [b][mt 0..63][ks 0..7][v 0..511][cpair 0..3][half 0..1]
__device__ float g_Vb[(size_t)Bn * 64 * 32768];
// P = exp(energy) in packed A-fragment tiles:
// [b][nt 0..31][mt 0..63][ (i_blk*8+ks)*128 + lane*4 + q ]   (8192 floats / tile)
__device__ float g_P [(size_t)Bn * 32 * 64 * 8192];
__device__ float g_L [(size_t)Bn * Nn];        // row sums
__device__ float g_scl[Vd];
__device__ float g_shf[Vd];

// ===========================================================================
// Helpers (portable ISA: sm_80-class mma.sync + cp.async only)
// ===========================================================================
__device__ __forceinline__ uint32_t smem_u32(const void* p) {
    uint32_t a;
    asm("{ .reg .u64 t; cvta.to.shared.u64 t, %1; cvt.u32.u64 %0, t; }" : "=r"(a) : "l"(p));
    return a;
}
__device__ __forceinline__ uint32_t f2tf32(float x) {
    uint32_t u;
    asm("cvt.rna.tf32.f32 %0, %1;" : "=r"(u) : "f"(x));
    return u;
}
__device__ __forceinline__ float tf32r(float x) { return __uint_as_float(f2tf32(x)); }
__device__ __forceinline__ void cp_async16(uint32_t saddr, const void* gaddr) {
    asm volatile("cp.async.ca.shared.global [%0], [%1], 16;"
                 :: "r"(saddr), "l"(gaddr) : "memory");
}
__device__ __forceinline__ void cp_commit() {
    asm volatile("cp.async.commit_group;" ::: "memory");
}
__device__ __forceinline__ void cp_wait1() {
    asm volatile("cp.async.wait_group 1;" ::: "memory");
}
__device__ __forceinline__ void cp_wait0() {
    asm volatile("cp.async.wait_group 0;" ::: "memory");
}
__device__ __forceinline__ void mma_tf32(float* d, const uint32_t* a, const uint32_t* b) {
    asm volatile(
        "mma.sync.aligned.m16n8k8.row.col.f32.tf32.tf32.f32 "
        "{%0,%1,%2,%3}, {%4,%5,%6,%7}, {%8,%9}, {%0,%1,%2,%3};"
        : "+f"(d[0]), "+f"(d[1]), "+f"(d[2]), "+f"(d[3])
        : "r"(a[0]), "r"(a[1]), "r"(a[2]), "r"(a[3]), "r"(b[0]), "r"(b[1]));
}
__device__ __forceinline__ void mma_bf16(float* d, const uint32_t* a, const uint32_t* b) {
    asm volatile(
        "mma.sync.aligned.m16n8k16.row.col.f32.bf16.bf16.f32 "
        "{%0,%1,%2,%3}, {%4,%5,%6,%7}, {%8,%9}, {%0,%1,%2,%3};"
        : "+f"(d[0]), "+f"(d[1]), "+f"(d[2]), "+f"(d[3])
        : "r"(a[0]), "r"(a[1]), "r"(a[2]), "r"(a[3]), "r"(b[0]), "r"(b[1]));
}
__device__ __forceinline__ uint32_t fu(float x) { return __float_as_uint(x); }
__device__ __forceinline__ uint32_t lds_u32(const char* p) { return *(const uint32_t*)p; }

// ===========================================================================
// BN scale/shift precompute
// ===========================================================================
__global__ void prep_kernel(const float* __restrict__ gamma, const float* __restrict__ beta,
                            const float* __restrict__ mean,  const float* __restrict__ var) {
    int i = threadIdx.x;
    if (i < Vd) {
        float s = gamma[i] * rsqrtf(var[i] + 1e-5f);
        g_scl[i] = s;
        g_shf[i] = beta[i] - mean[i] * s;
    }
}

// ===========================================================================
// Q+K projection merged (SIMT fp32, accurate) -> bf16 hi/lo split outputs
// grid (Nn/64, 2, Bn): blockIdx.y = 0 -> Q, 1 -> K
// ===========================================================================
__global__ __launch_bounds__(256) void qk_proj_kernel(
    const float* __restrict__ x,
    const float* __restrict__ Wq, const float* __restrict__ bq,
    const float* __restrict__ Wk, const float* __restrict__ bk) {
    __shared__ float Xs[16][65];
    __shared__ float Ws[64][17];
    const int which = blockIdx.y;
    const float* W    = which ? Wk : Wq;
    const float* bias = which ? bk : bq;
    __nv_bfloat16* out_hi = which ? g_Kh : g_Qh;
    __nv_bfloat16* out_lo = which ? g_Kl : g_Ql;

    const int b  = blockIdx.z;
    const int n0 = blockIdx.x * 64;
    const int tid = threadIdx.x;
    const int tx = tid & 15, ty = tid >> 4;

    float acc[4][4] = {};
    const float* xb = x + (size_t)b * Cc * Nn;

    for (int c0 = 0; c0 < Cc; c0 += 16) {
        {
            int n_l = tid & 63, c_l = tid >> 6;
            #pragma unroll
            for (int it = 0; it < 4; it++)
                Xs[c_l + 4 * it][n_l] = xb[(size_t)(c0 + c_l + 4 * it) * Nn + n0 + n_l];
        }
        {
            int c_l = tid & 15, o_l = tid >> 4;
            #pragma unroll
            for (int it = 0; it < 4; it++)
                Ws[o_l + 16 * it][c_l] = W[(size_t)(o_l + 16 * it) * Cc + c0 + c_l];
        }
        __syncthreads();
        #pragma unroll
        for (int cc = 0; cc < 16; cc++) {
            float a[4], w[4];
            #pragma unroll
            for (int i = 0; i < 4; i++) a[i] = Xs[cc][ty + 16 * i];
            #pragma unroll
            for (int j = 0; j < 4; j++) w[j] = Ws[tx + 16 * j][cc];
            #pragma unroll
            for (int i = 0; i < 4; i++)
                #pragma unroll
                for (int j = 0; j < 4; j++)
                    acc[i][j] = fmaf(a[i], w[j], acc[i][j]);
        }
        __syncthreads();
    }

    #pragma unroll
    for (int i = 0; i < 4; i++) {
        int n = n0 + ty + 16 * i;
        #pragma unroll
        for (int j = 0; j < 4; j++) {
            int o = tx + 16 * j;
            float v  = acc[i][j] + bias[o];
            __nv_bfloat16 h = __float2bfloat16(v);
            __nv_bfloat16 l = __float2bfloat16(v - __bfloat162float(h));
            size_t idx = ((size_t)b * Nn + n) * Kd + o;
            out_hi[idx] = h;
            out_lo[idx] = l;
        }
    }
}

// ===========================================================================
// V projection on mma.sync tf32 (2-stage), epilogue -> packed g_Vb.
// Tile 128(n=m) x 128(o=v) x 32(c); 8 warps 2x4.
// ===========================================================================
static constexpr int V_OFX0 = 0;               // 32*136 = 4352 floats
static constexpr int V_OFX1 = 4352;
static constexpr int V_OFW0 = 8704;            // 128*36 = 4608 floats
static constexpr int V_OFW1 = 13312;
static constexpr int V_FLOATS = 17920;         // 71.7 KB

__device__ __forceinline__ void vproj_stage(uint32_t sbase, int buf,
                                            const float* xb, const float* W,
                                            int n0, int v0, int kc) {
    const int t = threadIdx.x;
    const uint32_t sX = sbase + (buf ? V_OFX1 : V_OFX0) * 4;
    const uint32_t sW = sbase + (buf ? V_OFW1 : V_OFW0) * 4;
    #pragma unroll
    for (int p = 0; p < 4; p++) {                 // X: 32 rows(c) x 32 f4
        int id = t + 256 * p, r = id >> 5, c4 = id & 31;
        cp_async16(sX + (uint32_t)(r * 136 + c4 * 4) * 4,
                   xb + (size_t)(kc * 32 + r) * Nn + n0 + c4 * 4);
    }
    #pragma unroll
    for (int p = 0; p < 4; p++) {                 // W: 128 rows(o) x 8 f4
        int id = t + 256 * p, r = id >> 3, c4 = id & 7;
        cp_async16(sW + (uint32_t)(r * 36 + c4 * 4) * 4,
                   W + (size_t)(v0 + r) * Cc + kc * 32 + c4 * 4);
    }
}

__global__ __launch_bounds__(256) void vproj_mma_kernel(const float* __restrict__ x,
                                                        const float* __restrict__ W) {
    extern __shared__ float sm[];
    const uint32_t sbase = smem_u32(sm);
    const int tid = threadIdx.x;
    const int wid = tid >> 5, lane = tid & 31;
    const int g = lane >> 2, c = lane & 3;
    const int wn = wid & 1, wv = wid >> 1;
    const int b  = blockIdx.z;
    const int n0 = blockIdx.y * 128;
    const int v0 = blockIdx.x * 128;
    const float* xb = x + (size_t)b * Cc * Nn;

    float acc[4][4][4] = {};

    vproj_stage(sbase, 0, xb, W, n0, v0, 0);
    cp_commit();

    for (int kc = 0; kc < Cc / 32; kc++) {
        const int cur = kc & 1;
        if (kc + 1 < Cc / 32) {
            vproj_stage(sbase, cur ^ 1, xb, W, n0, v0, kc + 1);
            cp_commit();
            cp_wait1();
        } else {
            cp_wait0();
        }
        __syncthreads();

        const float* Xs = sm + (cur ? V_OFX1 : V_OFX0);
        const float* Ws = sm + (cur ? V_OFW1 : V_OFW0);

        #pragma unroll
        for (int ks = 0; ks < 4; ks++) {
            uint32_t af[4][4];
            #pragma unroll
            for (int i = 0; i < 4; i++) {
                const float* ap = Xs + (ks * 8 + c) * 136 + wn * 64 + i * 16 + g;
                af[i][0] = f2tf32(ap[0]);
                af[i][1] = f2tf32(ap[8]);
                af[i][2] = f2tf32(ap[4 * 136]);
                af[i][3] = f2tf32(ap[4 * 136 + 8]);
            }
            uint32_t bf[4][2];
            #pragma unroll
            for (int j = 0; j < 4; j++) {
                const float* bp = Ws + (wv * 32 + j * 8 + g) * 36 + ks * 8 + c;
                bf[j][0] = f2tf32(bp[0]);
                bf[j][1] = f2tf32(bp[4]);
            }
            #pragma unroll
            for (int i = 0; i < 4; i++)
                #pragma unroll
                for (int j = 0; j < 4; j++)
                    mma_tf32(acc[i][j], af[i], bf[j]);
        }
        __syncthreads();
    }

    // Epilogue: BN+ReLU, tf32-round, write packed B-pair layout g_Vb.
    // m = n0 + wn*64 + i*16 + g (+8), v = v0 + wv*32 + j*8 + 2c (+1)
    #pragma unroll
    for (int j = 0; j < 4; j++) {
        const int vv = v0 + wv * 32 + j * 8 + 2 * c;
        const float s0 = g_scl[vv],     h0 = g_shf[vv];
        const float s1 = g_scl[vv + 1], h1 = g_shf[vv + 1];
        #pragma unroll
        for (int i = 0; i < 4; i++) {
            const int mt = blockIdx.y * 2 + wn;     // (n0 + wn*64 + i*16)>>6
            const int ks0 = i * 2;
            float e00 = tf32r(fmaxf(fmaf(acc[i][j][0], s0, h0), 0.0f));
            float e01 = tf32r(fmaxf(fmaf(acc[i][j][1], s1, h1), 0.0f));
            float e10 = tf32r(fmaxf(fmaf(acc[i][j][2], s0, h0), 0.0f));
            float e11 = tf32r(fmaxf(fmaf(acc[i][j][3], s1, h1), 0.0f));
            size_t a0 = ((size_t)b * 64 + mt) * 32768 + (size_t)ks0 * 4096
                      + (size_t)vv * 8 + (g & 3) * 2 + (g >> 2);
            g_Vb[a0]            = e00;
            g_Vb[a0 + 8]        = e01;
            g_Vb[a0 + 4096]     = e10;
            g_Vb[a0 + 4096 + 8] = e11;
        }
    }
}

// ===========================================================================
// Energy on mma.sync BF16, 3-term hi/lo split; epilogue writes packed
// A-fragment tiles of g_P (+ row sums g_L).
// grid (Nn/128, Bn), block 256, warps 2(n) x 4(m).
// ===========================================================================
static constexpr int E_QH  = 0;                 // 128*144
static constexpr int E_QL  = 18432;
static constexpr int E_KH0 = 36864;             // 64*144 each
static constexpr int E_KH1 = 46080;
static constexpr int E_KL0 = 55296;
static constexpr int E_KL1 = 64512;
static constexpr int E_BYTES = 73728;

__global__ __launch_bounds__(256) void energy_mma_kernel() {
    extern __shared__ char smc[];
    __shared__ float sL[4][128];
    const uint32_t sbase = smem_u32(smc);
    const int tid = threadIdx.x;
    const int wid = tid >> 5, lane = tid & 31;
    const int g = lane >> 2, c = lane & 3;
    const int wn = wid & 1, wv = wid >> 1;
    const int b  = blockIdx.y;
    const int nt = blockIdx.x;
    const int n0 = nt * 128;

    const size_t qoff = ((size_t)b * Nn + n0) * Kd;
    const size_t koff = (size_t)b * Nn * Kd;

    #pragma unroll
    for (int p = 0; p < 4; p++) {
        int id = tid + 256 * p, r = id >> 3, c8 = id & 7;
        cp_async16(sbase + E_QH + r * 144 + c8 * 16, g_Qh + qoff + (size_t)r * Kd + c8 * 8);
        cp_async16(sbase + E_QL + r * 144 + c8 * 16, g_Ql + qoff + (size_t)r * Kd + c8 * 8);
    }
    #pragma unroll
    for (int p = 0; p < 2; p++) {
        int id = tid + 256 * p, r = id >> 3, c8 = id & 7;
        cp_async16(sbase + E_KH0 + r * 144 + c8 * 16, g_Kh + koff + (size_t)r * Kd + c8 * 8);
        cp_async16(sbase + E_KL0 + r * 144 + c8 * 16, g_Kl + koff + (size_t)r * Kd + c8 * 8);
    }
    cp_commit();

    float rsum[4][2] = {};

    for (int mc = 0; mc < 64; mc++) {
        const int cur = mc & 1;
        if (mc + 1 < 64) {
            const uint32_t kh = sbase + ((mc + 1) & 1 ? E_KH1 : E_KH0);
            const uint32_t kl = sbase + ((mc + 1) & 1 ? E_KL1 : E_KL0);
            #pragma unroll
            for (int p = 0; p < 2; p++) {
                int id = tid + 256 * p, r = id >> 3, c8 = id & 7;
                cp_async16(kh + r * 144 + c8 * 16,
                           g_Kh + koff + (size_t)((mc + 1) * 64 + r) * Kd + c8 * 8);
                cp_async16(kl + r * 144 + c8 * 16,
                           g_Kl + koff + (size_t)((mc + 1) * 64 + r) * Kd + c8 * 8);
            }
            cp_commit();
            cp_wait1();
        } else {
            cp_wait0();
        }
        __syncthreads();

        const char* QH = smc + E_QH;
        const char* QL = smc + E_QL;
        const char* KH = smc + (cur ? E_KH1 : E_KH0);
        const char* KL = smc + (cur ? E_KL1 : E_KL0);

        float acc[4][2][4] = {};
        #pragma unroll
        for (int ks = 0; ks < 4; ks++) {          // 4 x k16 covers Kd=64
            uint32_t ah[4][4], al[4][4];
            #pragma unroll
            for (int i = 0; i < 4; i++) {
                const int off = (wn * 64 + i * 16 + g) * 144 + ks * 32 + c * 4;
                ah[i][0] = lds_u32(QH + off);
                ah[i][1] = lds_u32(QH + off + 8 * 144);
                ah[i][2] = lds_u32(QH + off + 16);
                ah[i][3] = lds_u32(QH + off + 8 * 144 + 16);
                al[i][0] = lds_u32(QL + off);
                al[i][1] = lds_u32(QL + off + 8 * 144);
                al[i][2] = lds_u32(QL + off + 16);
                al[i][3] = lds_u32(QL + off + 8 * 144 + 16);
            }
            uint32_t bh[2][2], bl[2][2];
            #pragma unroll
            for (int j = 0; j < 2; j++) {
                const int off = (wv * 16 + j * 8 + g) * 144 + ks * 32 + c * 4;
                bh[j][0] = lds_u32(KH + off);
                bh[j][1] = lds_u32(KH + off + 16);
                bl[j][0] = lds_u32(KL + off);
                bl[j][1] = lds_u32(KL + off + 16);
            }
            #pragma unroll
            for (int i = 0; i < 4; i++)
                #pragma unroll
                for (int j = 0; j < 2; j++) {
                    mma_bf16(acc[i][j], ah[i], bh[j]);
                    mma_bf16(acc[i][j], ah[i], bl[j]);
                    mma_bf16(acc[i][j], al[i], bh[j]);
                }
        }
        __syncthreads();

        // Epilogue: exp, tf32-round, write packed A-fragment tile.
        const size_t tile0 = (((size_t)b * 32 + nt) * 64 + mc) * 8192;
        #pragma unroll
        for (int i = 0; i < 4; i++) {
            const int i_blk = wn * 4 + i;
            #pragma unroll
            for (int j = 0; j < 2; j++) {
                const int ks = wv * 2 + j;
                float e00 = tf32r(__expf(acc[i][j][0]));
                float e01 = tf32r(__expf(acc[i][j][1]));
                float e10 = tf32r(__expf(acc[i][j][2]));
                float e11 = tf32r(__expf(acc[i][j][3]));
                size_t off = tile0 + (size_t)((i_blk * 8 + ks) * 128
                           + (g * 4 + (c & 1) * 2) * 4 + (c >> 1) * 2);
                *(float2*)&g_P[off]     = make_float2(e00, e10);
                *(float2*)&g_P[off + 4] = make_float2(e01, e11);
                rsum[i][0] += e00 + e01;
                rsum[i][1] += e10 + e11;
            }
        }
    }

    #pragma unroll
    for (int i = 0; i < 4; i++)
        #pragma unroll
        for (int r = 0; r < 2; r++) {
            float v = rsum[i][r];
            v += __shfl_xor_sync(0xffffffffu, v, 1);
            v += __shfl_xor_sync(0xffffffffu, v, 2);
            rsum[i][r] = v;
        }
    if (c == 0) {
        #pragma unroll
        for (int i = 0; i < 4; i++) {
            sL[wv][wn * 64 + i * 16 + g]     = rsum[i][0];
            sL[wv][wn * 64 + i * 16 + g + 8] = rsum[i][1];
        }
    }
    __syncthreads();
    if (tid < 128)
        g_L[(size_t)b * Nn + n0 + tid] = sL[0][tid] + sL[1][tid] + sL[2][tid] + sL[3][tid];
}

// ===========================================================================
// PV GEMM (mma.sync tf32, packed operands, no cvt, LDS.128/LDS.64 frags):
//   out[b][v][n] = (1/L[n]) * sum_m P[n][m] Vb[m][v]
// Block 128(n) x 128(v), warp tile 64x32 (2x4 warps), K-chunk 32, 2-stage.
// SMEM floats: A stages @ {0, 4096} (16KB), B stages @ {8192, 12288} (16KB).
// Total 64KB -> 2 CTAs/SM (16 warps).
// ===========================================================================
static constexpr int AV_BYTES = 65536;

__device__ __forceinline__ void av_stage(uint32_t sbase, int buf,
                                         const float* gA, const float* gB,
                                         int v0, int ch) {
    const int t = threadIdx.x;
    const int mt = ch >> 1, half = ch & 1;
    const uint32_t sA = sbase + (buf ? 4096u : 0u) * 4;
    const uint32_t sB = sbase + (8192u + buf * 4096u) * 4;
    const float* gAt = gA + (size_t)mt * 8192 + half * 512;
    const float* gBt = gB + (size_t)mt * 32768 + (size_t)half * 4 * 4096 + (size_t)v0 * 8;
    #pragma unroll
    for (int p = 0; p < 4; p++) {   // A: 32 blk-rows (i_blk*4+ksl) x 128 floats
        int id = t + 256 * p, blk = id >> 5, w = id & 31;
        int i_blk = blk >> 2, ksl = blk & 3;
        cp_async16(sA + (uint32_t)(blk * 128 + w * 4) * 4,
                   gAt + (size_t)i_blk * 1024 + ksl * 128 + w * 4);
    }
    #pragma unroll
    for (int p = 0; p < 4; p++) {   // B: 4 ksl x 1024 floats (128 v x 8)
        int id = t + 256 * p, ksl = id >> 8, w = id & 255;
        cp_async16(sB + (uint32_t)(ksl * 1024 + w * 4) * 4,
                   gBt + (size_t)ksl * 4096 + w * 4);
    }
}

__global__ __launch_bounds__(256, 2) void av_mma_kernel(float* __restrict__ out) {
    extern __shared__ float sm[];
    const uint32_t sbase = smem_u32(sm);
    const int tid  = threadIdx.x;
    const int wid  = tid >> 5, lane = tid & 31;
    const int g = lane >> 2, c = lane & 3;
    const int wn = wid & 1, wv = wid >> 1;
    const int b  = blockIdx.z;
    const int nt = blockIdx.y;
    const int n0 = nt * 128;
    const int v0 = blockIdx.x * 128;

    const float* gA = g_P  + (((size_t)b * 32 + nt) * 64) * 8192;
    const float* gB = g_Vb + ((size_t)b * 64) * 32768;

    float acc[4][4][4] = {};

    av_stage(sbase, 0, gA, gB, v0, 0);
    cp_commit();

    for (int ch = 0; ch < 128; ch++) {
        const int cur = ch & 1;
        if (ch + 1 < 128) {
            av_stage(sbase, cur ^ 1, gA, gB, v0, ch + 1);
            cp_commit();
            cp_wait1();
        } else {
            cp_wait0();
        }
        __syncthreads();

        const float* As = sm + cur * 4096;
        const float* Bs = sm + 8192 + cur * 4096;

        #pragma unroll
        for (int ksl = 0; ksl < 4; ksl++) {
            uint32_t af[4][4];
            #pragma unroll
            for (int i = 0; i < 4; i++) {
                float4 v4 = *(const float4*)(As + ((wn * 4 + i) * 4 + ksl) * 128 + lane * 4);
                af[i][0] = fu(v4.x); af[i][1] = fu(v4.y);
                af[i][2] = fu(v4.z); af[i][3] = fu(v4.w);
            }
            uint32_t bf[4][2];
            #pragma unroll
            for (int j = 0; j < 4; j++) {
                float2 v2 = *(const float2*)(Bs + ksl * 1024 + (wv * 32 + j * 8 + g) * 8 + c * 2);
                bf[j][0] = fu(v2.x); bf[j][1] = fu(v2.y);
            }
            #pragma unroll
            for (int i = 0; i < 4; i++)
                #pragma unroll
                for (int j = 0; j < 4; j++)
                    mma_tf32(acc[i][j], af[i], bf[j]);
        }
        __syncthreads();
    }

    #pragma unroll
    for (int i = 0; i < 4; i++) {
        const int n_lo = n0 + wn * 64 + i * 16 + g;
        const float linv_lo = 1.0f / g_L[(size_t)b * Nn + n_lo];
        const float linv_hi = 1.0f / g_L[(size_t)b * Nn + n_lo + 8];
        #pragma unroll
        for (int j = 0; j < 4; j++) {
            const int v = v0 + wv * 32 + j * 8 + c * 2;
            float* o0p = out + ((size_t)b * Vd + v)     * Nn + n_lo;
            float* o1p = out + ((size_t)b * Vd + v + 1) * Nn + n_lo;
            o0p[0] = acc[i][j][0] * linv_lo;
            o1p[0] = acc[i][j][1] * linv_lo;
            o0p[8] = acc[i][j][2] * linv_hi;
            o1p[8] = acc[i][j][3] * linv_hi;
        }
    }
}

// ===========================================================================
extern "C" void kernel_launch(void* const* d_in, const int* in_sizes, int n_in,
                              void* d_out, int out_size) {
    const float* x     = (const float*)d_in[0];
    const float* Wq    = (const float*)d_in[1];
    const float* bq    = (const float*)d_in[2];
    const float* Wk    = (const float*)d_in[3];
    const float* bk    = (const float*)d_in[4];
    const float* Wv    = (const float*)d_in[5];
    const float* gamma = (const float*)d_in[6];
    const float* beta  = (const float*)d_in[7];
    const float* mean  = (const float*)d_in[8];
    const float* var   = (const float*)d_in[9];
    float* out = (float*)d_out;

    static int smem_set = 0;
    if (!smem_set) {
        cudaFuncSetAttribute(vproj_mma_kernel,
                             cudaFuncAttributeMaxDynamicSharedMemorySize, V_FLOATS * 4);
        cudaFuncSetAttribute(energy_mma_kernel,
                             cudaFuncAttributeMaxDynamicSharedMemorySize, E_BYTES);
        cudaFuncSetAttribute(av_mma_kernel,
                             cudaFuncAttributeMaxDynamicSharedMemorySize, AV_BYTES);
        smem_set = 1;
    }

    prep_kernel<<<1, 512>>>(gamma, beta, mean, var);

    qk_proj_kernel<<<dim3(Nn / 64, 2, Bn), 256>>>(x, Wq, bq, Wk, bk);
    vproj_mma_kernel<<<dim3(Vd / 128, Nn / 128, Bn), 256, V_FLOATS * 4>>>(x, Wv);

    energy_mma_kernel<<<dim3(Nn / 128, Bn), 256, E_BYTES>>>();

    av_mma_kernel<<<dim3(Vd / 128, Nn / 128, Bn), 256, AV_BYTES>>>(out);
}

// round 9
// speedup vs baseline: 1.3981x; 1.0540x over previous
#include <cuda_runtime.h>
#include <cuda_bf16.h>
#include <cstdint>
#include <cstddef>

static constexpr int Bn = 8;
static constexpr int Cc = 512;
static constexpr int Nn = 4096;   // H*W
static constexpr int Kd = 64;
static constexpr int Vd = 512;

// Scratch (device globals)
__device__ __nv_bfloat16 g_Xh[(size_t)Bn * Nn * Cc];   // x transposed [b][n][c] bf16 hi
__device__ __nv_bfloat16 g_Xl[(size_t)Bn * Nn * Cc];   // residual lo
__device__ __nv_bfloat16 g_Wh[128 * Cc];               // [Wq;Wk] rows o 0..127, bf16 hi
__device__ __nv_bfloat16 g_Wl[128 * Cc];
__device__ __nv_bfloat16 g_Qh[(size_t)Bn * Nn * Kd];   // [b][n][k] bf16 hi
__device__ __nv_bfloat16 g_Ql[(size_t)Bn * Nn * Kd];
__device__ __nv_bfloat16 g_Kh[(size_t)Bn * Nn * Kd];
__device__ __nv_bfloat16 g_Kl[(size_t)Bn * Nn * Kd];
// V in packed B-pair layout: [b][mt 0..63][ks 0..7][v 0..511][cpair 0..3][half 0..1]
__device__ float g_Vb[(size_t)Bn * 64 * 32768];
// P = exp(energy) in packed A-fragment tiles:
// [b][nt 0..31][mt 0..63][ (i_blk*8+ks)*128 + lane*4 + q ]   (8192 floats / tile)
__device__ float g_P [(size_t)Bn * 32 * 64 * 8192];
__device__ float g_L [(size_t)Bn * Nn];        // row sums
__device__ float g_scl[Vd];
__device__ float g_shf[Vd];

// ===========================================================================
// Helpers (portable ISA: sm_80-class mma.sync + cp.async only)
// ===========================================================================
__device__ __forceinline__ uint32_t smem_u32(const void* p) {
    uint32_t a;
    asm("{ .reg .u64 t; cvta.to.shared.u64 t, %1; cvt.u32.u64 %0, t; }" : "=r"(a) : "l"(p));
    return a;
}
__device__ __forceinline__ uint32_t f2tf32(float x) {
    uint32_t u;
    asm("cvt.rna.tf32.f32 %0, %1;" : "=r"(u) : "f"(x));
    return u;
}
__device__ __forceinline__ float tf32r(float x) { return __uint_as_float(f2tf32(x)); }
__device__ __forceinline__ void cp_async16(uint32_t saddr, const void* gaddr) {
    asm volatile("cp.async.ca.shared.global [%0], [%1], 16;"
                 :: "r"(saddr), "l"(gaddr) : "memory");
}
__device__ __forceinline__ void cp_commit() {
    asm volatile("cp.async.commit_group;" ::: "memory");
}
__device__ __forceinline__ void cp_wait1() {
    asm volatile("cp.async.wait_group 1;" ::: "memory");
}
__device__ __forceinline__ void cp_wait0() {
    asm volatile("cp.async.wait_group 0;" ::: "memory");
}
__device__ __forceinline__ void mma_tf32(float* d, const uint32_t* a, const uint32_t* b) {
    asm volatile(
        "mma.sync.aligned.m16n8k8.row.col.f32.tf32.tf32.f32 "
        "{%0,%1,%2,%3}, {%4,%5,%6,%7}, {%8,%9}, {%0,%1,%2,%3};"
        : "+f"(d[0]), "+f"(d[1]), "+f"(d[2]), "+f"(d[3])
        : "r"(a[0]), "r"(a[1]), "r"(a[2]), "r"(a[3]), "r"(b[0]), "r"(b[1]));
}
__device__ __forceinline__ void mma_bf16(float* d, const uint32_t* a, const uint32_t* b) {
    asm volatile(
        "mma.sync.aligned.m16n8k16.row.col.f32.bf16.bf16.f32 "
        "{%0,%1,%2,%3}, {%4,%5,%6,%7}, {%8,%9}, {%0,%1,%2,%3};"
        : "+f"(d[0]), "+f"(d[1]), "+f"(d[2]), "+f"(d[3])
        : "r"(a[0]), "r"(a[1]), "r"(a[2]), "r"(a[3]), "r"(b[0]), "r"(b[1]));
}
__device__ __forceinline__ uint32_t fu(float x) { return __float_as_uint(x); }
__device__ __forceinline__ uint32_t lds_u32(const char* p) { return *(const uint32_t*)p; }
__device__ __forceinline__ uint32_t bfcat(__nv_bfloat16 lo, __nv_bfloat16 hi) {
    __nv_bfloat162 t; t.x = lo; t.y = hi;
    return *(uint32_t*)&t;
}

// ===========================================================================
// BN scale/shift precompute
// ===========================================================================
__global__ void prep_kernel(const float* __restrict__ gamma, const float* __restrict__ beta,
                            const float* __restrict__ mean,  const float* __restrict__ var) {
    int i = threadIdx.x;
    if (i < Vd) {
        float s = gamma[i] * rsqrtf(var[i] + 1e-5f);
        g_scl[i] = s;
        g_shf[i] = beta[i] - mean[i] * s;
    }
}

// ===========================================================================
// W split: [Wq;Wk] -> bf16 hi/lo, rows o 0..127
// ===========================================================================
__global__ __launch_bounds__(256) void wsplit_kernel(const float* __restrict__ Wq,
                                                     const float* __restrict__ Wk) {
    int id = blockIdx.x * 256 + threadIdx.x;       // 128*512 = 65536
    int o = id >> 9, cc = id & 511;
    float v = (o < 64) ? Wq[o * Cc + cc] : Wk[(o - 64) * Cc + cc];
    __nv_bfloat16 h = __float2bfloat16(v);
    g_Wh[id] = h;
    g_Wl[id] = __float2bfloat16(v - __bfloat162float(h));
}

// ===========================================================================
// X split + transpose: x[b][c][n] fp32 -> g_Xh/g_Xl [b][n][c] bf16
// ===========================================================================
__global__ __launch_bounds__(256) void xsplit_kernel(const float* __restrict__ x) {
    __shared__ float t[32][33];
    const int b = blockIdx.z, n0 = blockIdx.x * 32, c0 = blockIdx.y * 32;
    const int tx = threadIdx.x & 31, ty = threadIdx.x >> 5;
    #pragma unroll
    for (int p = 0; p < 4; p++)
        t[ty + 8 * p][tx] = x[((size_t)b * Cc + c0 + ty + 8 * p) * Nn + n0 + tx];
    __syncthreads();
    #pragma unroll
    for (int p = 0; p < 4; p++) {
        float v = t[tx][ty + 8 * p];
        __nv_bfloat16 h = __float2bfloat16(v);
        __nv_bfloat16 l = __float2bfloat16(v - __bfloat162float(h));
        size_t idx = ((size_t)b * Nn + n0 + ty + 8 * p) * Cc + c0 + tx;
        g_Xh[idx] = h;
        g_Xl[idx] = l;
    }
}

// ===========================================================================
// Q+K projection on mma.sync bf16 (3-term split, fp32-grade accuracy):
//   D[n][o] = sum_c X[n][c] * W[o][c], o 0..63 -> Q (+bq), 64..127 -> K (+bk)
// CTA: 64n x 128o x 512c (chunks of 32); warps 2n x 4o, warp 32x32.
// SMEM rows padded to 80B (conflict-free frag loads).
// ===========================================================================
static constexpr int QK_XH0 = 0,     QK_XH1 = 5120;
static constexpr int QK_XL0 = 10240, QK_XL1 = 15360;
static constexpr int QK_WH0 = 20480, QK_WH1 = 30720;
static constexpr int QK_WL0 = 40960, QK_WL1 = 51200;
static constexpr int QK_BYTES = 61440;

__device__ __forceinline__ void qk_stage(uint32_t sbase, int buf, int b, int n0, int kc) {
    const int t = threadIdx.x;
    const uint32_t xh = sbase + (buf ? QK_XH1 : QK_XH0);
    const uint32_t xl = sbase + (buf ? QK_XL1 : QK_XL0);
    const uint32_t wh = sbase + (buf ? QK_WH1 : QK_WH0);
    const uint32_t wl = sbase + (buf ? QK_WL1 : QK_WL0);
    {
        int r = t >> 2, c4 = t & 3;   // X: 64 rows x 4 x 16B
        size_t src = ((size_t)b * Nn + n0 + r) * Cc + kc * 32 + c4 * 8;
        cp_async16(xh + r * 80 + c4 * 16, g_Xh + src);
        cp_async16(xl + r * 80 + c4 * 16, g_Xl + src);
    }
    #pragma unroll
    for (int p = 0; p < 2; p++) {     // W: 128 rows x 4 x 16B
        int id = t + 256 * p, r = id >> 2, c4 = id & 3;
        size_t src = (size_t)r * Cc + kc * 32 + c4 * 8;
        cp_async16(wh + r * 80 + c4 * 16, g_Wh + src);
        cp_async16(wl + r * 80 + c4 * 16, g_Wl + src);
    }
}

__global__ __launch_bounds__(256) void qk_mma_kernel(const float* __restrict__ bq,
                                                     const float* __restrict__ bk) {
    extern __shared__ char smc[];
    const uint32_t sbase = smem_u32(smc);
    const int tid = threadIdx.x;
    const int wid = tid >> 5, lane = tid & 31;
    const int g = lane >> 2, c = lane & 3;
    const int wn = wid & 1, wo = wid >> 1;
    const int b  = blockIdx.z;
    const int n0 = blockIdx.x * 64;

    float acc[2][4][4] = {};

    qk_stage(sbase, 0, b, n0, 0);
    cp_commit();

    for (int kc = 0; kc < 16; kc++) {
        const int cur = kc & 1;
        if (kc + 1 < 16) {
            qk_stage(sbase, cur ^ 1, b, n0, kc + 1);
            cp_commit();
            cp_wait1();
        } else {
            cp_wait0();
        }
        __syncthreads();

        const char* XH = smc + (cur ? QK_XH1 : QK_XH0);
        const char* XL = smc + (cur ? QK_XL1 : QK_XL0);
        const char* WH = smc + (cur ? QK_WH1 : QK_WH0);
        const char* WL = smc + (cur ? QK_WL1 : QK_WL0);

        #pragma unroll
        for (int ks = 0; ks < 2; ks++) {
            uint32_t ah[2][4], al[2][4];
            #pragma unroll
            for (int i = 0; i < 2; i++) {
                const int off = (wn * 32 + i * 16 + g) * 80 + ks * 32 + c * 4;
                ah[i][0] = lds_u32(XH + off);
                ah[i][1] = lds_u32(XH + off + 8 * 80);
                ah[i][2] = lds_u32(XH + off + 16);
                ah[i][3] = lds_u32(XH + off + 8 * 80 + 16);
                al[i][0] = lds_u32(XL + off);
                al[i][1] = lds_u32(XL + off + 8 * 80);
                al[i][2] = lds_u32(XL + off + 16);
                al[i][3] = lds_u32(XL + off + 8 * 80 + 16);
            }
            uint32_t bh[4][2], bl[4][2];
            #pragma unroll
            for (int j = 0; j < 4; j++) {
                const int off = (wo * 32 + j * 8 + g) * 80 + ks * 32 + c * 4;
                bh[j][0] = lds_u32(WH + off);
                bh[j][1] = lds_u32(WH + off + 16);
                bl[j][0] = lds_u32(WL + off);
                bl[j][1] = lds_u32(WL + off + 16);
            }
            #pragma unroll
            for (int i = 0; i < 2; i++)
                #pragma unroll
                for (int j = 0; j < 4; j++) {
                    mma_bf16(acc[i][j], ah[i], bh[j]);
                    mma_bf16(acc[i][j], ah[i], bl[j]);
                    mma_bf16(acc[i][j], al[i], bh[j]);
                }
        }
        __syncthreads();
    }

    // Epilogue: add bias, split hi/lo bf16, store. Warp-uniform Q/K side.
    const int which = wo >> 1;                       // 0: Q, 1: K
    __nv_bfloat16* dh = which ? g_Kh : g_Qh;
    __nv_bfloat16* dl = which ? g_Kl : g_Ql;
    const float* bias = which ? bk : bq;
    #pragma unroll
    for (int i = 0; i < 2; i++) {
        const int n_lo = n0 + wn * 32 + i * 16 + g;
        #pragma unroll
        for (int j = 0; j < 4; j++) {
            const int o = (wo * 32 + j * 8 + 2 * c) & 63;
            const float b0 = bias[o], b1 = bias[o + 1];
            float v00 = acc[i][j][0] + b0, v01 = acc[i][j][1] + b1;
            float v10 = acc[i][j][2] + b0, v11 = acc[i][j][3] + b1;
            __nv_bfloat16 h00 = __float2bfloat16(v00), h01 = __float2bfloat16(v01);
            __nv_bfloat16 h10 = __float2bfloat16(v10), h11 = __float2bfloat16(v11);
            __nv_bfloat16 l00 = __float2bfloat16(v00 - __bfloat162float(h00));
            __nv_bfloat16 l01 = __float2bfloat16(v01 - __bfloat162float(h01));
            __nv_bfloat16 l10 = __float2bfloat16(v10 - __bfloat162float(h10));
            __nv_bfloat16 l11 = __float2bfloat16(v11 - __bfloat162float(h11));
            size_t r0 = ((size_t)b * Nn + n_lo) * Kd + o;
            size_t r1 = ((size_t)b * Nn + n_lo + 8) * Kd + o;
            *(uint32_t*)&dh[r0] = bfcat(h00, h01);
            *(uint32_t*)&dh[r1] = bfcat(h10, h11);
            *(uint32_t*)&dl[r0] = bfcat(l00, l01);
            *(uint32_t*)&dl[r1] = bfcat(l10, l11);
        }
    }
}

// ===========================================================================
// V projection on mma.sync tf32 (2-stage), epilogue -> packed g_Vb.
// Tile 128(n=m) x 128(o=v) x 32(c); 8 warps 2x4.   (unchanged from R8)
// ===========================================================================
static constexpr int V_OFX0 = 0;
static constexpr int V_OFX1 = 4352;
static constexpr int V_OFW0 = 8704;
static constexpr int V_OFW1 = 13312;
static constexpr int V_FLOATS = 17920;

__device__ __forceinline__ void vproj_stage(uint32_t sbase, int buf,
                                            const float* xb, const float* W,
                                            int n0, int v0, int kc) {
    const int t = threadIdx.x;
    const uint32_t sX = sbase + (buf ? V_OFX1 : V_OFX0) * 4;
    const uint32_t sW = sbase + (buf ? V_OFW1 : V_OFW0) * 4;
    #pragma unroll
    for (int p = 0; p < 4; p++) {
        int id = t + 256 * p, r = id >> 5, c4 = id & 31;
        cp_async16(sX + (uint32_t)(r * 136 + c4 * 4) * 4,
                   xb + (size_t)(kc * 32 + r) * Nn + n0 + c4 * 4);
    }
    #pragma unroll
    for (int p = 0; p < 4; p++) {
        int id = t + 256 * p, r = id >> 3, c4 = id & 7;
        cp_async16(sW + (uint32_t)(r * 36 + c4 * 4) * 4,
                   W + (size_t)(v0 + r) * Cc + kc * 32 + c4 * 4);
    }
}

__global__ __launch_bounds__(256) void vproj_mma_kernel(const float* __restrict__ x,
                                                        const float* __restrict__ W) {
    extern __shared__ float sm[];
    const uint32_t sbase = smem_u32(sm);
    const int tid = threadIdx.x;
    const int wid = tid >> 5, lane = tid & 31;
    const int g = lane >> 2, c = lane & 3;
    const int wn = wid & 1, wv = wid >> 1;
    const int b  = blockIdx.z;
    const int n0 = blockIdx.y * 128;
    const int v0 = blockIdx.x * 128;
    const float* xb = x + (size_t)b * Cc * Nn;

    float acc[4][4][4] = {};

    vproj_stage(sbase, 0, xb, W, n0, v0, 0);
    cp_commit();

    for (int kc = 0; kc < Cc / 32; kc++) {
        const int cur = kc & 1;
        if (kc + 1 < Cc / 32) {
            vproj_stage(sbase, cur ^ 1, xb, W, n0, v0, kc + 1);
            cp_commit();
            cp_wait1();
        } else {
            cp_wait0();
        }
        __syncthreads();

        const float* Xs = sm + (cur ? V_OFX1 : V_OFX0);
        const float* Ws = sm + (cur ? V_OFW1 : V_OFW0);

        #pragma unroll
        for (int ks = 0; ks < 4; ks++) {
            uint32_t af[4][4];
            #pragma unroll
            for (int i = 0; i < 4; i++) {
                const float* ap = Xs + (ks * 8 + c) * 136 + wn * 64 + i * 16 + g;
                af[i][0] = f2tf32(ap[0]);
                af[i][1] = f2tf32(ap[8]);
                af[i][2] = f2tf32(ap[4 * 136]);
                af[i][3] = f2tf32(ap[4 * 136 + 8]);
            }
            uint32_t bf[4][2];
            #pragma unroll
            for (int j = 0; j < 4; j++) {
                const float* bp = Ws + (wv * 32 + j * 8 + g) * 36 + ks * 8 + c;
                bf[j][0] = f2tf32(bp[0]);
                bf[j][1] = f2tf32(bp[4]);
            }
            #pragma unroll
            for (int i = 0; i < 4; i++)
                #pragma unroll
                for (int j = 0; j < 4; j++)
                    mma_tf32(acc[i][j], af[i], bf[j]);
        }
        __syncthreads();
    }

    #pragma unroll
    for (int j = 0; j < 4; j++) {
        const int vv = v0 + wv * 32 + j * 8 + 2 * c;
        const float s0 = g_scl[vv],     h0 = g_shf[vv];
        const float s1 = g_scl[vv + 1], h1 = g_shf[vv + 1];
        #pragma unroll
        for (int i = 0; i < 4; i++) {
            const int mt = blockIdx.y * 2 + wn;
            const int ks0 = i * 2;
            float e00 = tf32r(fmaxf(fmaf(acc[i][j][0], s0, h0), 0.0f));
            float e01 = tf32r(fmaxf(fmaf(acc[i][j][1], s1, h1), 0.0f));
            float e10 = tf32r(fmaxf(fmaf(acc[i][j][2], s0, h0), 0.0f));
            float e11 = tf32r(fmaxf(fmaf(acc[i][j][3], s1, h1), 0.0f));
            size_t a0 = ((size_t)b * 64 + mt) * 32768 + (size_t)ks0 * 4096
                      + (size_t)vv * 8 + (g & 3) * 2 + (g >> 2);
            g_Vb[a0]            = e00;
            g_Vb[a0 + 8]        = e01;
            g_Vb[a0 + 4096]     = e10;
            g_Vb[a0 + 4096 + 8] = e11;
        }
    }
}

// ===========================================================================
// Energy on mma.sync BF16, 3-term hi/lo split; n-tile 64 for occupancy.
// grid (Nn/64, Bn), block 256, warps 2(n) x 4(m), warp tile 32n x 16m.
// ===========================================================================
static constexpr int E_QH  = 0;                 // 64*144
static constexpr int E_QL  = 9216;
static constexpr int E_KH0 = 18432;             // 64*144 each
static constexpr int E_KH1 = 27648;
static constexpr int E_KL0 = 36864;
static constexpr int E_KL1 = 46080;
static constexpr int E_BYTES = 55296;

__global__ __launch_bounds__(256) void energy_mma_kernel() {
    extern __shared__ char smc[];
    __shared__ float sL[4][64];
    const uint32_t sbase = smem_u32(smc);
    const int tid = threadIdx.x;
    const int wid = tid >> 5, lane = tid & 31;
    const int g = lane >> 2, c = lane & 3;
    const int wn = wid & 1, wv = wid >> 1;
    const int b  = blockIdx.y;
    const int n0 = blockIdx.x * 64;
    const int nt = blockIdx.x >> 1;
    const int half = blockIdx.x & 1;

    const size_t qoff = ((size_t)b * Nn + n0) * Kd;
    const size_t koff = (size_t)b * Nn * Kd;

    #pragma unroll
    for (int p = 0; p < 2; p++) {                 // Q: 64 rows x 8 x 16B (hi+lo)
        int id = tid + 256 * p, r = id >> 3, c8 = id & 7;
        cp_async16(sbase + E_QH + r * 144 + c8 * 16, g_Qh + qoff + (size_t)r * Kd + c8 * 8);
        cp_async16(sbase + E_QL + r * 144 + c8 * 16, g_Ql + qoff + (size_t)r * Kd + c8 * 8);
    }
    #pragma unroll
    for (int p = 0; p < 2; p++) {                 // K chunk 0
        int id = tid + 256 * p, r = id >> 3, c8 = id & 7;
        cp_async16(sbase + E_KH0 + r * 144 + c8 * 16, g_Kh + koff + (size_t)r * Kd + c8 * 8);
        cp_async16(sbase + E_KL0 + r * 144 + c8 * 16, g_Kl + koff + (size_t)r * Kd + c8 * 8);
    }
    cp_commit();

    float rsum[2][2] = {};

    for (int mc = 0; mc < 64; mc++) {
        const int cur = mc & 1;
        if (mc + 1 < 64) {
            const uint32_t kh = sbase + ((mc + 1) & 1 ? E_KH1 : E_KH0);
            const uint32_t kl = sbase + ((mc + 1) & 1 ? E_KL1 : E_KL0);
            #pragma unroll
            for (int p = 0; p < 2; p++) {
                int id = tid + 256 * p, r = id >> 3, c8 = id & 7;
                cp_async16(kh + r * 144 + c8 * 16,
                           g_Kh + koff + (size_t)((mc + 1) * 64 + r) * Kd + c8 * 8);
                cp_async16(kl + r * 144 + c8 * 16,
                           g_Kl + koff + (size_t)((mc + 1) * 64 + r) * Kd + c8 * 8);
            }
            cp_commit();
            cp_wait1();
        } else {
            cp_wait0();
        }
        __syncthreads();

        const char* QH = smc + E_QH;
        const char* QL = smc + E_QL;
        const char* KH = smc + (cur ? E_KH1 : E_KH0);
        const char* KL = smc + (cur ? E_KL1 : E_KL0);

        float acc[2][2][4] = {};
        #pragma unroll
        for (int ks = 0; ks < 4; ks++) {
            uint32_t ah[2][4], al[2][4];
            #pragma unroll
            for (int i = 0; i < 2; i++) {
                const int off = (wn * 32 + i * 16 + g) * 144 + ks * 32 + c * 4;
                ah[i][0] = lds_u32(QH + off);
                ah[i][1] = lds_u32(QH + off + 8 * 144);
                ah[i][2] = lds_u32(QH + off + 16);
                ah[i][3] = lds_u32(QH + off + 8 * 144 + 16);
                al[i][0] = lds_u32(QL + off);
                al[i][1] = lds_u32(QL + off + 8 * 144);
                al[i][2] = lds_u32(QL + off + 16);
                al[i][3] = lds_u32(QL + off + 8 * 144 + 16);
            }
            uint32_t bh[2][2], bl[2][2];
            #pragma unroll
            for (int j = 0; j < 2; j++) {
                const int off = (wv * 16 + j * 8 + g) * 144 + ks * 32 + c * 4;
                bh[j][0] = lds_u32(KH + off);
                bh[j][1] = lds_u32(KH + off + 16);
                bl[j][0] = lds_u32(KL + off);
                bl[j][1] = lds_u32(KL + off + 16);
            }
            #pragma unroll
            for (int i = 0; i < 2; i++)
                #pragma unroll
                for (int j = 0; j < 2; j++) {
                    mma_bf16(acc[i][j], ah[i], bh[j]);
                    mma_bf16(acc[i][j], ah[i], bl[j]);
                    mma_bf16(acc[i][j], al[i], bh[j]);
                }
        }
        __syncthreads();

        // Epilogue: exp, tf32-round, write packed A-fragment tile.
        const size_t tile0 = (((size_t)b * 32 + nt) * 64 + mc) * 8192;
        #pragma unroll
        for (int i = 0; i < 2; i++) {
            const int i_blk = half * 4 + wn * 2 + i;
            #pragma unroll
            for (int j = 0; j < 2; j++) {
                const int ks = wv * 2 + j;
                float e00 = tf32r(__expf(acc[i][j][0]));
                float e01 = tf32r(__expf(acc[i][j][1]));
                float e10 = tf32r(__expf(acc[i][j][2]));
                float e11 = tf32r(__expf(acc[i][j][3]));
                size_t off = tile0 + (size_t)((i_blk * 8 + ks) * 128
                           + (g * 4 + (c & 1) * 2) * 4 + (c >> 1) * 2);
                *(float2*)&g_P[off]     = make_float2(e00, e10);
                *(float2*)&g_P[off + 4] = make_float2(e01, e11);
                rsum[i][0] += e00 + e01;
                rsum[i][1] += e10 + e11;
            }
        }
    }

    #pragma unroll
    for (int i = 0; i < 2; i++)
        #pragma unroll
        for (int r = 0; r < 2; r++) {
            float v = rsum[i][r];
            v += __shfl_xor_sync(0xffffffffu, v, 1);
            v += __shfl_xor_sync(0xffffffffu, v, 2);
            rsum[i][r] = v;
        }
    if (c == 0) {
        #pragma unroll
        for (int i = 0; i < 2; i++) {
            sL[wv][wn * 32 + i * 16 + g]     = rsum[i][0];
            sL[wv][wn * 32 + i * 16 + g + 8] = rsum[i][1];
        }
    }
    __syncthreads();
    if (tid < 64)
        g_L[(size_t)b * Nn + n0 + tid] = sL[0][tid] + sL[1][tid] + sL[2][tid] + sL[3][tid];
}

// ===========================================================================
// PV GEMM (mma.sync tf32, packed operands, no cvt):   (unchanged from R8)
// Block 128(n) x 128(v), warp 64x32, K-chunk 32, 2-stage, 64KB -> 2 CTAs/SM.
// ===========================================================================
static constexpr int AV_BYTES = 65536;

__device__ __forceinline__ void av_stage(uint32_t sbase, int buf,
                                         const float* gA, const float* gB,
                                         int v0, int ch) {
    const int t = threadIdx.x;
    const int mt = ch >> 1, half = ch & 1;
    const uint32_t sA = sbase + (buf ? 4096u : 0u) * 4;
    const uint32_t sB = sbase + (8192u + buf * 4096u) * 4;
    const float* gAt = gA + (size_t)mt * 8192 + half * 512;
    const float* gBt = gB + (size_t)mt * 32768 + (size_t)half * 4 * 4096 + (size_t)v0 * 8;
    #pragma unroll
    for (int p = 0; p < 4; p++) {
        int id = t + 256 * p, blk = id >> 5, w = id & 31;
        int i_blk = blk >> 2, ksl = blk & 3;
        cp_async16(sA + (uint32_t)(blk * 128 + w * 4) * 4,
                   gAt + (size_t)i_blk * 1024 + ksl * 128 + w * 4);
    }
    #pragma unroll
    for (int p = 0; p < 4; p++) {
        int id = t + 256 * p, ksl = id >> 8, w = id & 255;
        cp_async16(sB + (uint32_t)(ksl * 1024 + w * 4) * 4,
                   gBt + (size_t)ksl * 4096 + w * 4);
    }
}

__global__ __launch_bounds__(256, 2) void av_mma_kernel(float* __restrict__ out) {
    extern __shared__ float sm[];
    const uint32_t sbase = smem_u32(sm);
    const int tid  = threadIdx.x;
    const int wid  = tid >> 5, lane = tid & 31;
    const int g = lane >> 2, c = lane & 3;
    const int wn = wid & 1, wv = wid >> 1;
    const int b  = blockIdx.z;
    const int nt = blockIdx.y;
    const int n0 = nt * 128;
    const int v0 = blockIdx.x * 128;

    const float* gA = g_P  + (((size_t)b * 32 + nt) * 64) * 8192;
    const float* gB = g_Vb + ((size_t)b * 64) * 32768;

    float acc[4][4][4] = {};

    av_stage(sbase, 0, gA, gB, v0, 0);
    cp_commit();

    for (int ch = 0; ch < 128; ch++) {
        const int cur = ch & 1;
        if (ch + 1 < 128) {
            av_stage(sbase, cur ^ 1, gA, gB, v0, ch + 1);
            cp_commit();
            cp_wait1();
        } else {
            cp_wait0();
        }
        __syncthreads();

        const float* As = sm + cur * 4096;
        const float* Bs = sm + 8192 + cur * 4096;

        #pragma unroll
        for (int ksl = 0; ksl < 4; ksl++) {
            uint32_t af[4][4];
            #pragma unroll
            for (int i = 0; i < 4; i++) {
                float4 v4 = *(const float4*)(As + ((wn * 4 + i) * 4 + ksl) * 128 + lane * 4);
                af[i][0] = fu(v4.x); af[i][1] = fu(v4.y);
                af[i][2] = fu(v4.z); af[i][3] = fu(v4.w);
            }
            uint32_t bf[4][2];
            #pragma unroll
            for (int j = 0; j < 4; j++) {
                float2 v2 = *(const float2*)(Bs + ksl * 1024 + (wv * 32 + j * 8 + g) * 8 + c * 2);
                bf[j][0] = fu(v2.x); bf[j][1] = fu(v2.y);
            }
            #pragma unroll
            for (int i = 0; i < 4; i++)
                #pragma unroll
                for (int j = 0; j < 4; j++)
                    mma_tf32(acc[i][j], af[i], bf[j]);
        }
        __syncthreads();
    }

    #pragma unroll
    for (int i = 0; i < 4; i++) {
        const int n_lo = n0 + wn * 64 + i * 16 + g;
        const float linv_lo = 1.0f / g_L[(size_t)b * Nn + n_lo];
        const float linv_hi = 1.0f / g_L[(size_t)b * Nn + n_lo + 8];
        #pragma unroll
        for (int j = 0; j < 4; j++) {
            const int v = v0 + wv * 32 + j * 8 + c * 2;
            float* o0p = out + ((size_t)b * Vd + v)     * Nn + n_lo;
            float* o1p = out + ((size_t)b * Vd + v + 1) * Nn + n_lo;
            o0p[0] = acc[i][j][0] * linv_lo;
            o1p[0] = acc[i][j][1] * linv_lo;
            o0p[8] = acc[i][j][2] * linv_hi;
            o1p[8] = acc[i][j][3] * linv_hi;
        }
    }
}

// ===========================================================================
extern "C" void kernel_launch(void* const* d_in, const int* in_sizes, int n_in,
                              void* d_out, int out_size) {
    const float* x     = (const float*)d_in[0];
    const float* Wq    = (const float*)d_in[1];
    const float* bq    = (const float*)d_in[2];
    const float* Wk    = (const float*)d_in[3];
    const float* bk    = (const float*)d_in[4];
    const float* Wv    = (const float*)d_in[5];
    const float* gamma = (const float*)d_in[6];
    const float* beta  = (const float*)d_in[7];
    const float* mean  = (const float*)d_in[8];
    const float* var   = (const float*)d_in[9];
    float* out = (float*)d_out;

    static int smem_set = 0;
    if (!smem_set) {
        cudaFuncSetAttribute(qk_mma_kernel,
                             cudaFuncAttributeMaxDynamicSharedMemorySize, QK_BYTES);
        cudaFuncSetAttribute(vproj_mma_kernel,
                             cudaFuncAttributeMaxDynamicSharedMemorySize, V_FLOATS * 4);
        cudaFuncSetAttribute(energy_mma_kernel,
                             cudaFuncAttributeMaxDynamicSharedMemorySize, E_BYTES);
        cudaFuncSetAttribute(av_mma_kernel,
                             cudaFuncAttributeMaxDynamicSharedMemorySize, AV_BYTES);
        smem_set = 1;
    }

    prep_kernel<<<1, 512>>>(gamma, beta, mean, var);
    wsplit_kernel<<<256, 256>>>(Wq, Wk);
    xsplit_kernel<<<dim3(Nn / 32, Cc / 32, Bn), 256>>>(x);

    qk_mma_kernel<<<dim3(Nn / 64, 1, Bn), 256, QK_BYTES>>>(bq, bk);
    vproj_mma_kernel<<<dim3(Vd / 128, Nn / 128, Bn), 256, V_FLOATS * 4>>>(x, Wv);

    energy_mma_kernel<<<dim3(Nn / 64, Bn), 256, E_BYTES>>>();

    av_mma_kernel<<<dim3(Vd / 128, Nn / 128, Bn), 256, AV_BYTES>>>(out);
}

// round 10
// speedup vs baseline: 1.8812x; 1.3456x over previous
#include <cuda_runtime.h>
#include <cuda_bf16.h>
#include <cuda_fp16.h>
#include <cstdint>
#include <cstddef>

static constexpr int Bn = 8;
static constexpr int Cc = 512;
static constexpr int Nn = 4096;   // H*W
static constexpr int Kd = 64;
static constexpr int Vd = 512;

// Scratch (device globals)
__device__ __nv_bfloat16 g_Xh[(size_t)Bn * Nn * Cc];   // x transposed [b][n][c] bf16 hi
__device__ __nv_bfloat16 g_Xl[(size_t)Bn * Nn * Cc];
__device__ __nv_bfloat16 g_Wh[128 * Cc];               // [Wq;Wk]
__device__ __nv_bfloat16 g_Wl[128 * Cc];
__device__ __nv_bfloat16 g_Qh[(size_t)Bn * Nn * Kd];
__device__ __nv_bfloat16 g_Ql[(size_t)Bn * Nn * Kd];
__device__ __nv_bfloat16 g_Kh[(size_t)Bn * Nn * Kd];
__device__ __nv_bfloat16 g_Kl[(size_t)Bn * Nn * Kd];
// V fp16 packed as av B-fragments: per [b][mt 0..63]: [kb 0..3][vj 0..63][lane][2] u32
__device__ uint32_t g_Vh[(size_t)Bn * 64 * 16384];
// P fp16 packed as av A-fragments: per [b][nt 0..31][mt 0..63]:
//   [i_blk 0..7][kb 0..3][lane 0..31][4] u32   (4096 u32 = 16KB per tile)
__device__ uint32_t g_Pf[(size_t)Bn * 32 * 64 * 4096];
__device__ float g_M [(size_t)Bn * Nn];        // row maxes (approx)
__device__ float g_L [(size_t)Bn * Nn];        // row sums of shifted exps
__device__ float g_scl[Vd];
__device__ float g_shf[Vd];

// ===========================================================================
// Helpers (portable ISA: sm_80-class mma.sync + cp.async only)
// ===========================================================================
__device__ __forceinline__ uint32_t smem_u32(const void* p) {
    uint32_t a;
    asm("{ .reg .u64 t; cvta.to.shared.u64 t, %1; cvt.u32.u64 %0, t; }" : "=r"(a) : "l"(p));
    return a;
}
__device__ __forceinline__ uint32_t f2tf32(float x) {
    uint32_t u;
    asm("cvt.rna.tf32.f32 %0, %1;" : "=r"(u) : "f"(x));
    return u;
}
__device__ __forceinline__ void cp_async16(uint32_t saddr, const void* gaddr) {
    asm volatile("cp.async.ca.shared.global [%0], [%1], 16;"
                 :: "r"(saddr), "l"(gaddr) : "memory");
}
__device__ __forceinline__ void cp_commit() {
    asm volatile("cp.async.commit_group;" ::: "memory");
}
__device__ __forceinline__ void cp_wait1() {
    asm volatile("cp.async.wait_group 1;" ::: "memory");
}
__device__ __forceinline__ void cp_wait0() {
    asm volatile("cp.async.wait_group 0;" ::: "memory");
}
__device__ __forceinline__ void mma_tf32(float* d, const uint32_t* a, const uint32_t* b) {
    asm volatile(
        "mma.sync.aligned.m16n8k8.row.col.f32.tf32.tf32.f32 "
        "{%0,%1,%2,%3}, {%4,%5,%6,%7}, {%8,%9}, {%0,%1,%2,%3};"
        : "+f"(d[0]), "+f"(d[1]), "+f"(d[2]), "+f"(d[3])
        : "r"(a[0]), "r"(a[1]), "r"(a[2]), "r"(a[3]), "r"(b[0]), "r"(b[1]));
}
__device__ __forceinline__ void mma_bf16(float* d, const uint32_t* a, const uint32_t* b) {
    asm volatile(
        "mma.sync.aligned.m16n8k16.row.col.f32.bf16.bf16.f32 "
        "{%0,%1,%2,%3}, {%4,%5,%6,%7}, {%8,%9}, {%0,%1,%2,%3};"
        : "+f"(d[0]), "+f"(d[1]), "+f"(d[2]), "+f"(d[3])
        : "r"(a[0]), "r"(a[1]), "r"(a[2]), "r"(a[3]), "r"(b[0]), "r"(b[1]));
}
__device__ __forceinline__ void mma_f16(float* d, const uint32_t* a, const uint32_t* b) {
    asm volatile(
        "mma.sync.aligned.m16n8k16.row.col.f32.f16.f16.f32 "
        "{%0,%1,%2,%3}, {%4,%5,%6,%7}, {%8,%9}, {%0,%1,%2,%3};"
        : "+f"(d[0]), "+f"(d[1]), "+f"(d[2]), "+f"(d[3])
        : "r"(a[0]), "r"(a[1]), "r"(a[2]), "r"(a[3]), "r"(b[0]), "r"(b[1]));
}
__device__ __forceinline__ uint32_t fu(float x) { return __float_as_uint(x); }
__device__ __forceinline__ uint32_t lds_u32(const char* p) { return *(const uint32_t*)p; }
__device__ __forceinline__ uint32_t bfcat(__nv_bfloat16 lo, __nv_bfloat16 hi) {
    __nv_bfloat162 t; t.x = lo; t.y = hi;
    return *(uint32_t*)&t;
}
__device__ __forceinline__ uint32_t hfcat(__half lo, __half hi) {
    __half2 t; t.x = lo; t.y = hi;
    return *(uint32_t*)&t;
}

// ===========================================================================
// BN scale/shift precompute
// ===========================================================================
__global__ void prep_kernel(const float* __restrict__ gamma, const float* __restrict__ beta,
                            const float* __restrict__ mean,  const float* __restrict__ var) {
    int i = threadIdx.x;
    if (i < Vd) {
        float s = gamma[i] * rsqrtf(var[i] + 1e-5f);
        g_scl[i] = s;
        g_shf[i] = beta[i] - mean[i] * s;
    }
}

// ===========================================================================
// W split: [Wq;Wk] -> bf16 hi/lo
// ===========================================================================
__global__ __launch_bounds__(256) void wsplit_kernel(const float* __restrict__ Wq,
                                                     const float* __restrict__ Wk) {
    int id = blockIdx.x * 256 + threadIdx.x;
    int o = id >> 9, cc = id & 511;
    float v = (o < 64) ? Wq[o * Cc + cc] : Wk[(o - 64) * Cc + cc];
    __nv_bfloat16 h = __float2bfloat16(v);
    g_Wh[id] = h;
    g_Wl[id] = __float2bfloat16(v - __bfloat162float(h));
}

// ===========================================================================
// X split + transpose: x[b][c][n] fp32 -> g_Xh/g_Xl [b][n][c] bf16
// ===========================================================================
__global__ __launch_bounds__(256) void xsplit_kernel(const float* __restrict__ x) {
    __shared__ float t[32][33];
    const int b = blockIdx.z, n0 = blockIdx.x * 32, c0 = blockIdx.y * 32;
    const int tx = threadIdx.x & 31, ty = threadIdx.x >> 5;
    #pragma unroll
    for (int p = 0; p < 4; p++)
        t[ty + 8 * p][tx] = x[((size_t)b * Cc + c0 + ty + 8 * p) * Nn + n0 + tx];
    __syncthreads();
    #pragma unroll
    for (int p = 0; p < 4; p++) {
        float v = t[tx][ty + 8 * p];
        __nv_bfloat16 h = __float2bfloat16(v);
        __nv_bfloat16 l = __float2bfloat16(v - __bfloat162float(h));
        size_t idx = ((size_t)b * Nn + n0 + ty + 8 * p) * Cc + c0 + tx;
        g_Xh[idx] = h;
        g_Xl[idx] = l;
    }
}

// ===========================================================================
// Q+K projection on mma.sync bf16 (3-term split)   (unchanged from R9)
// ===========================================================================
static constexpr int QK_XH0 = 0,     QK_XH1 = 5120;
static constexpr int QK_XL0 = 10240, QK_XL1 = 15360;
static constexpr int QK_WH0 = 20480, QK_WH1 = 30720;
static constexpr int QK_WL0 = 40960, QK_WL1 = 51200;
static constexpr int QK_BYTES = 61440;

__device__ __forceinline__ void qk_stage(uint32_t sbase, int buf, int b, int n0, int kc) {
    const int t = threadIdx.x;
    const uint32_t xh = sbase + (buf ? QK_XH1 : QK_XH0);
    const uint32_t xl = sbase + (buf ? QK_XL1 : QK_XL0);
    const uint32_t wh = sbase + (buf ? QK_WH1 : QK_WH0);
    const uint32_t wl = sbase + (buf ? QK_WL1 : QK_WL0);
    {
        int r = t >> 2, c4 = t & 3;
        size_t src = ((size_t)b * Nn + n0 + r) * Cc + kc * 32 + c4 * 8;
        cp_async16(xh + r * 80 + c4 * 16, g_Xh + src);
        cp_async16(xl + r * 80 + c4 * 16, g_Xl + src);
    }
    #pragma unroll
    for (int p = 0; p < 2; p++) {
        int id = t + 256 * p, r = id >> 2, c4 = id & 3;
        size_t src = (size_t)r * Cc + kc * 32 + c4 * 8;
        cp_async16(wh + r * 80 + c4 * 16, g_Wh + src);
        cp_async16(wl + r * 80 + c4 * 16, g_Wl + src);
    }
}

__global__ __launch_bounds__(256) void qk_mma_kernel(const float* __restrict__ bq,
                                                     const float* __restrict__ bk) {
    extern __shared__ char smc[];
    const uint32_t sbase = smem_u32(smc);
    const int tid = threadIdx.x;
    const int wid = tid >> 5, lane = tid & 31;
    const int g = lane >> 2, c = lane & 3;
    const int wn = wid & 1, wo = wid >> 1;
    const int b  = blockIdx.z;
    const int n0 = blockIdx.x * 64;

    float acc[2][4][4] = {};

    qk_stage(sbase, 0, b, n0, 0);
    cp_commit();

    for (int kc = 0; kc < 16; kc++) {
        const int cur = kc & 1;
        if (kc + 1 < 16) {
            qk_stage(sbase, cur ^ 1, b, n0, kc + 1);
            cp_commit();
            cp_wait1();
        } else {
            cp_wait0();
        }
        __syncthreads();

        const char* XH = smc + (cur ? QK_XH1 : QK_XH0);
        const char* XL = smc + (cur ? QK_XL1 : QK_XL0);
        const char* WH = smc + (cur ? QK_WH1 : QK_WH0);
        const char* WL = smc + (cur ? QK_WL1 : QK_WL0);

        #pragma unroll
        for (int ks = 0; ks < 2; ks++) {
            uint32_t ah[2][4], al[2][4];
            #pragma unroll
            for (int i = 0; i < 2; i++) {
                const int off = (wn * 32 + i * 16 + g) * 80 + ks * 32 + c * 4;
                ah[i][0] = lds_u32(XH + off);
                ah[i][1] = lds_u32(XH + off + 8 * 80);
                ah[i][2] = lds_u32(XH + off + 16);
                ah[i][3] = lds_u32(XH + off + 8 * 80 + 16);
                al[i][0] = lds_u32(XL + off);
                al[i][1] = lds_u32(XL + off + 8 * 80);
                al[i][2] = lds_u32(XL + off + 16);
                al[i][3] = lds_u32(XL + off + 8 * 80 + 16);
            }
            uint32_t bh[4][2], bl[4][2];
            #pragma unroll
            for (int j = 0; j < 4; j++) {
                const int off = (wo * 32 + j * 8 + g) * 80 + ks * 32 + c * 4;
                bh[j][0] = lds_u32(WH + off);
                bh[j][1] = lds_u32(WH + off + 16);
                bl[j][0] = lds_u32(WL + off);
                bl[j][1] = lds_u32(WL + off + 16);
            }
            #pragma unroll
            for (int i = 0; i < 2; i++)
                #pragma unroll
                for (int j = 0; j < 4; j++) {
                    mma_bf16(acc[i][j], ah[i], bh[j]);
                    mma_bf16(acc[i][j], ah[i], bl[j]);
                    mma_bf16(acc[i][j], al[i], bh[j]);
                }
        }
        __syncthreads();
    }

    const int which = wo >> 1;
    __nv_bfloat16* dh = which ? g_Kh : g_Qh;
    __nv_bfloat16* dl = which ? g_Kl : g_Ql;
    const float* bias = which ? bk : bq;
    #pragma unroll
    for (int i = 0; i < 2; i++) {
        const int n_lo = n0 + wn * 32 + i * 16 + g;
        #pragma unroll
        for (int j = 0; j < 4; j++) {
            const int o = (wo * 32 + j * 8 + 2 * c) & 63;
            const float b0 = bias[o], b1 = bias[o + 1];
            float v00 = acc[i][j][0] + b0, v01 = acc[i][j][1] + b1;
            float v10 = acc[i][j][2] + b0, v11 = acc[i][j][3] + b1;
            __nv_bfloat16 h00 = __float2bfloat16(v00), h01 = __float2bfloat16(v01);
            __nv_bfloat16 h10 = __float2bfloat16(v10), h11 = __float2bfloat16(v11);
            __nv_bfloat16 l00 = __float2bfloat16(v00 - __bfloat162float(h00));
            __nv_bfloat16 l01 = __float2bfloat16(v01 - __bfloat162float(h01));
            __nv_bfloat16 l10 = __float2bfloat16(v10 - __bfloat162float(h10));
            __nv_bfloat16 l11 = __float2bfloat16(v11 - __bfloat162float(h11));
            size_t r0 = ((size_t)b * Nn + n_lo) * Kd + o;
            size_t r1 = ((size_t)b * Nn + n_lo + 8) * Kd + o;
            *(uint32_t*)&dh[r0] = bfcat(h00, h01);
            *(uint32_t*)&dh[r1] = bfcat(h10, h11);
            *(uint32_t*)&dl[r0] = bfcat(l00, l01);
            *(uint32_t*)&dl[r1] = bfcat(l10, l11);
        }
    }
}

// ===========================================================================
// Max pass: M[b][n] ~= max_m (q.k) via hi-only bf16 QK^T (no stores).
// grid (Nn/64, Bn), block 256, warps 2(n) x 4(m), warp 32x16.
// ===========================================================================
static constexpr int MX_QH  = 0;                // 64*144
static constexpr int MX_KH0 = 9216;
static constexpr int MX_KH1 = 18432;
static constexpr int MX_BYTES = 27648;

__global__ __launch_bounds__(256) void maxpass_kernel() {
    extern __shared__ char smc[];
    __shared__ float sM[4][64];
    const uint32_t sbase = smem_u32(smc);
    const int tid = threadIdx.x;
    const int wid = tid >> 5, lane = tid & 31;
    const int g = lane >> 2, c = lane & 3;
    const int wn = wid & 1, wv = wid >> 1;
    const int b  = blockIdx.y;
    const int n0 = blockIdx.x * 64;

    const size_t qoff = ((size_t)b * Nn + n0) * Kd;
    const size_t koff = (size_t)b * Nn * Kd;

    #pragma unroll
    for (int p = 0; p < 2; p++) {
        int id = tid + 256 * p, r = id >> 3, c8 = id & 7;
        cp_async16(sbase + MX_QH + r * 144 + c8 * 16, g_Qh + qoff + (size_t)r * Kd + c8 * 8);
    }
    {
        int r = tid >> 2, c8 = (tid & 3) * 2;    // 64 rows x 4 x 32B
        cp_async16(sbase + MX_KH0 + r * 144 + c8 * 16, g_Kh + koff + (size_t)r * Kd + c8 * 8);
        cp_async16(sbase + MX_KH0 + r * 144 + (c8 + 1) * 16, g_Kh + koff + (size_t)r * Kd + (c8 + 1) * 8);
    }
    cp_commit();

    float mx[2][2] = { { -1e30f, -1e30f }, { -1e30f, -1e30f } };

    for (int mc = 0; mc < 64; mc++) {
        const int cur = mc & 1;
        if (mc + 1 < 64) {
            const uint32_t kh = sbase + ((mc + 1) & 1 ? MX_KH1 : MX_KH0);
            int r = tid >> 2, c8 = (tid & 3) * 2;
            cp_async16(kh + r * 144 + c8 * 16,
                       g_Kh + koff + (size_t)((mc + 1) * 64 + r) * Kd + c8 * 8);
            cp_async16(kh + r * 144 + (c8 + 1) * 16,
                       g_Kh + koff + (size_t)((mc + 1) * 64 + r) * Kd + (c8 + 1) * 8);
            cp_commit();
            cp_wait1();
        } else {
            cp_wait0();
        }
        __syncthreads();

        const char* QH = smc + MX_QH;
        const char* KH = smc + (cur ? MX_KH1 : MX_KH0);

        float acc[2][2][4] = {};
        #pragma unroll
        for (int ks = 0; ks < 4; ks++) {
            uint32_t ah[2][4];
            #pragma unroll
            for (int i = 0; i < 2; i++) {
                const int off = (wn * 32 + i * 16 + g) * 144 + ks * 32 + c * 4;
                ah[i][0] = lds_u32(QH + off);
                ah[i][1] = lds_u32(QH + off + 8 * 144);
                ah[i][2] = lds_u32(QH + off + 16);
                ah[i][3] = lds_u32(QH + off + 8 * 144 + 16);
            }
            uint32_t bh[2][2];
            #pragma unroll
            for (int j = 0; j < 2; j++) {
                const int off = (wv * 16 + j * 8 + g) * 144 + ks * 32 + c * 4;
                bh[j][0] = lds_u32(KH + off);
                bh[j][1] = lds_u32(KH + off + 16);
            }
            #pragma unroll
            for (int i = 0; i < 2; i++)
                #pragma unroll
                for (int j = 0; j < 2; j++)
                    mma_bf16(acc[i][j], ah[i], bh[j]);
        }
        __syncthreads();

        #pragma unroll
        for (int i = 0; i < 2; i++)
            #pragma unroll
            for (int j = 0; j < 2; j++) {
                mx[i][0] = fmaxf(mx[i][0], fmaxf(acc[i][j][0], acc[i][j][1]));
                mx[i][1] = fmaxf(mx[i][1], fmaxf(acc[i][j][2], acc[i][j][3]));
            }
    }

    #pragma unroll
    for (int i = 0; i < 2; i++)
        #pragma unroll
        for (int r = 0; r < 2; r++) {
            float v = mx[i][r];
            v = fmaxf(v, __shfl_xor_sync(0xffffffffu, v, 1));
            v = fmaxf(v, __shfl_xor_sync(0xffffffffu, v, 2));
            mx[i][r] = v;
        }
    if (c == 0) {
        #pragma unroll
        for (int i = 0; i < 2; i++) {
            sM[wv][wn * 32 + i * 16 + g]     = mx[i][0];
            sM[wv][wn * 32 + i * 16 + g + 8] = mx[i][1];
        }
    }
    __syncthreads();
    if (tid < 64)
        g_M[(size_t)b * Nn + n0 + tid] =
            fmaxf(fmaxf(sM[0][tid], sM[1][tid]), fmaxf(sM[2][tid], sM[3][tid]));
}

// ===========================================================================
// V projection on mma.sync tf32, swapped roles (A = W rows v, B = X cols m):
//   D[v][m] -> BN+ReLU -> fp16 -> packed g_Vh (av B-fragments)
// Tile 128(v) x 128(m) x 32(c); warps wn -> v 64-block, wv -> m 32-block.
// ===========================================================================
static constexpr int V_OFX0 = 0;               // 32*136 floats (X: [c][m])
static constexpr int V_OFX1 = 4352;
static constexpr int V_OFW0 = 8704;            // 128*36 floats (W: [v][c])
static constexpr int V_OFW1 = 13312;
static constexpr int V_FLOATS = 17920;

__device__ __forceinline__ void vproj_stage(uint32_t sbase, int buf,
                                            const float* xb, const float* W,
                                            int m0, int v0, int kc) {
    const int t = threadIdx.x;
    const uint32_t sX = sbase + (buf ? V_OFX1 : V_OFX0) * 4;
    const uint32_t sW = sbase + (buf ? V_OFW1 : V_OFW0) * 4;
    #pragma unroll
    for (int p = 0; p < 4; p++) {
        int id = t + 256 * p, r = id >> 5, c4 = id & 31;
        cp_async16(sX + (uint32_t)(r * 136 + c4 * 4) * 4,
                   xb + (size_t)(kc * 32 + r) * Nn + m0 + c4 * 4);
    }
    #pragma unroll
    for (int p = 0; p < 4; p++) {
        int id = t + 256 * p, r = id >> 3, c4 = id & 7;
        cp_async16(sW + (uint32_t)(r * 36 + c4 * 4) * 4,
                   W + (size_t)(v0 + r) * Cc + kc * 32 + c4 * 4);
    }
}

__global__ __launch_bounds__(256) void vproj_mma_kernel(const float* __restrict__ x,
                                                        const float* __restrict__ W) {
    extern __shared__ float sm[];
    const uint32_t sbase = smem_u32(sm);
    const int tid = threadIdx.x;
    const int wid = tid >> 5, lane = tid & 31;
    const int g = lane >> 2, c = lane & 3;
    const int wn = wid & 1, wv = wid >> 1;
    const int b  = blockIdx.z;
    const int m0 = blockIdx.y * 128;
    const int v0 = blockIdx.x * 128;
    const float* xb = x + (size_t)b * Cc * Nn;

    float acc[4][4][4] = {};   // [i: v16][j: m8][frag]

    vproj_stage(sbase, 0, xb, W, m0, v0, 0);
    cp_commit();

    for (int kc = 0; kc < Cc / 32; kc++) {
        const int cur = kc & 1;
        if (kc + 1 < Cc / 32) {
            vproj_stage(sbase, cur ^ 1, xb, W, m0, v0, kc + 1);
            cp_commit();
            cp_wait1();
        } else {
            cp_wait0();
        }
        __syncthreads();

        const float* Xs = sm + (cur ? V_OFX1 : V_OFX0);
        const float* Ws = sm + (cur ? V_OFW1 : V_OFW0);

        #pragma unroll
        for (int ks = 0; ks < 4; ks++) {
            uint32_t af[4][4];
            #pragma unroll
            for (int i = 0; i < 4; i++) {     // A = W rows v
                const float* ap = Ws + (wn * 64 + i * 16 + g) * 36 + ks * 8 + c;
                af[i][0] = f2tf32(ap[0]);
                af[i][1] = f2tf32(ap[8 * 36]);
                af[i][2] = f2tf32(ap[4]);
                af[i][3] = f2tf32(ap[8 * 36 + 4]);
            }
            uint32_t bf[4][2];
            #pragma unroll
            for (int j = 0; j < 4; j++) {     // B = X cols m
                const float* bp = Xs + (ks * 8 + c) * 136 + wv * 32 + j * 8 + g;
                bf[j][0] = f2tf32(bp[0]);
                bf[j][1] = f2tf32(bp[4 * 136]);
            }
            #pragma unroll
            for (int i = 0; i < 4; i++)
                #pragma unroll
                for (int j = 0; j < 4; j++)
                    mma_tf32(acc[i][j], af[i], bf[j]);
        }
        __syncthreads();
    }

    // Epilogue: BN+ReLU (per v row), fp16, write packed B-fragments.
    const int mt = blockIdx.y * 2 + (wv >> 1);
    uint32_t* base = g_Vh + ((size_t)b * 64 + mt) * 16384;
    #pragma unroll
    for (int i = 0; i < 4; i++) {
        const int vg = v0 + wn * 64 + i * 16 + g;
        const float sg = g_scl[vg],     hg = g_shf[vg];
        const float s8 = g_scl[vg + 8], h8 = g_shf[vg + 8];
        const int vj = vg >> 3;
        #pragma unroll
        for (int j = 0; j < 4; j++) {
            const int kb = ((wv * 32 + j * 8) >> 4) & 3;
            const int lohi = j & 1;
            __half a0 = __float2half(fmaxf(fmaf(acc[i][j][0], sg, hg), 0.f));
            __half a1 = __float2half(fmaxf(fmaf(acc[i][j][1], sg, hg), 0.f));
            __half a2 = __float2half(fmaxf(fmaf(acc[i][j][2], s8, h8), 0.f));
            __half a3 = __float2half(fmaxf(fmaf(acc[i][j][3], s8, h8), 0.f));
            base[(size_t)kb * 4096 + (size_t)vj * 64 + lane * 2 + lohi]       = hfcat(a0, a1);
            base[(size_t)kb * 4096 + (size_t)(vj + 1) * 64 + lane * 2 + lohi] = hfcat(a2, a3);
        }
    }
}

// ===========================================================================
// Energy on mma.sync BF16 (3-term); epilogue: exp(l - M[n]) -> fp16 packed
// A-fragment tiles g_Pf, + row sums g_L.
// grid (Nn/64, Bn), block 256, warps 2(n) x 4(m), warp 32x16.
// ===========================================================================
static constexpr int E_QH  = 0;                 // 64*144
static constexpr int E_QL  = 9216;
static constexpr int E_KH0 = 18432;
static constexpr int E_KH1 = 27648;
static constexpr int E_KL0 = 36864;
static constexpr int E_KL1 = 46080;
static constexpr int E_BYTES = 55296;

__global__ __launch_bounds__(256) void energy_mma_kernel() {
    extern __shared__ char smc[];
    __shared__ float sL[4][64];
    const uint32_t sbase = smem_u32(smc);
    const int tid = threadIdx.x;
    const int wid = tid >> 5, lane = tid & 31;
    const int g = lane >> 2, c = lane & 3;
    const int wn = wid & 1, wv = wid >> 1;
    const int b  = blockIdx.y;
    const int n0 = blockIdx.x * 64;
    const int nt = blockIdx.x >> 1;
    const int half = blockIdx.x & 1;

    const size_t qoff = ((size_t)b * Nn + n0) * Kd;
    const size_t koff = (size_t)b * Nn * Kd;

    #pragma unroll
    for (int p = 0; p < 2; p++) {
        int id = tid + 256 * p, r = id >> 3, c8 = id & 7;
        cp_async16(sbase + E_QH + r * 144 + c8 * 16, g_Qh + qoff + (size_t)r * Kd + c8 * 8);
        cp_async16(sbase + E_QL + r * 144 + c8 * 16, g_Ql + qoff + (size_t)r * Kd + c8 * 8);
    }
    #pragma unroll
    for (int p = 0; p < 2; p++) {
        int id = tid + 256 * p, r = id >> 3, c8 = id & 7;
        cp_async16(sbase + E_KH0 + r * 144 + c8 * 16, g_Kh + koff + (size_t)r * Kd + c8 * 8);
        cp_async16(sbase + E_KL0 + r * 144 + c8 * 16, g_Kl + koff + (size_t)r * Kd + c8 * 8);
    }
    cp_commit();

    // Preload row maxes
    float Mv[2][2];
    #pragma unroll
    for (int i = 0; i < 2; i++) {
        Mv[i][0] = g_M[(size_t)b * Nn + n0 + wn * 32 + i * 16 + g];
        Mv[i][1] = g_M[(size_t)b * Nn + n0 + wn * 32 + i * 16 + g + 8];
    }

    float rsum[2][2] = {};

    for (int mc = 0; mc < 64; mc++) {
        const int cur = mc & 1;
        if (mc + 1 < 64) {
            const uint32_t kh = sbase + ((mc + 1) & 1 ? E_KH1 : E_KH0);
            const uint32_t kl = sbase + ((mc + 1) & 1 ? E_KL1 : E_KL0);
            #pragma unroll
            for (int p = 0; p < 2; p++) {
                int id = tid + 256 * p, r = id >> 3, c8 = id & 7;
                cp_async16(kh + r * 144 + c8 * 16,
                           g_Kh + koff + (size_t)((mc + 1) * 64 + r) * Kd + c8 * 8);
                cp_async16(kl + r * 144 + c8 * 16,
                           g_Kl + koff + (size_t)((mc + 1) * 64 + r) * Kd + c8 * 8);
            }
            cp_commit();
            cp_wait1();
        } else {
            cp_wait0();
        }
        __syncthreads();

        const char* QH = smc + E_QH;
        const char* QL = smc + E_QL;
        const char* KH = smc + (cur ? E_KH1 : E_KH0);
        const char* KL = smc + (cur ? E_KL1 : E_KL0);

        float acc[2][2][4] = {};
        #pragma unroll
        for (int ks = 0; ks < 4; ks++) {
            uint32_t ah[2][4], al[2][4];
            #pragma unroll
            for (int i = 0; i < 2; i++) {
                const int off = (wn * 32 + i * 16 + g) * 144 + ks * 32 + c * 4;
                ah[i][0] = lds_u32(QH + off);
                ah[i][1] = lds_u32(QH + off + 8 * 144);
                ah[i][2] = lds_u32(QH + off + 16);
                ah[i][3] = lds_u32(QH + off + 8 * 144 + 16);
                al[i][0] = lds_u32(QL + off);
                al[i][1] = lds_u32(QL + off + 8 * 144);
                al[i][2] = lds_u32(QL + off + 16);
                al[i][3] = lds_u32(QL + off + 8 * 144 + 16);
            }
            uint32_t bh[2][2], bl[2][2];
            #pragma unroll
            for (int j = 0; j < 2; j++) {
                const int off = (wv * 16 + j * 8 + g) * 144 + ks * 32 + c * 4;
                bh[j][0] = lds_u32(KH + off);
                bh[j][1] = lds_u32(KH + off + 16);
                bl[j][0] = lds_u32(KL + off);
                bl[j][1] = lds_u32(KL + off + 16);
            }
            #pragma unroll
            for (int i = 0; i < 2; i++)
                #pragma unroll
                for (int j = 0; j < 2; j++) {
                    mma_bf16(acc[i][j], ah[i], bh[j]);
                    mma_bf16(acc[i][j], ah[i], bl[j]);
                    mma_bf16(acc[i][j], al[i], bh[j]);
                }
        }
        __syncthreads();

        // Epilogue: shifted exp -> fp16, pack av A-fragments (uint4 per i).
        const size_t tile0 = (((size_t)b * 32 + nt) * 64 + mc) * 4096;
        #pragma unroll
        for (int i = 0; i < 2; i++) {
            const int i_blk = half * 4 + wn * 2 + i;
            __half h[2][4];
            #pragma unroll
            for (int j = 0; j < 2; j++) {
                h[j][0] = __float2half(__expf(acc[i][j][0] - Mv[i][0]));
                h[j][1] = __float2half(__expf(acc[i][j][1] - Mv[i][0]));
                h[j][2] = __float2half(__expf(acc[i][j][2] - Mv[i][1]));
                h[j][3] = __float2half(__expf(acc[i][j][3] - Mv[i][1]));
                rsum[i][0] += __half2float(h[j][0]) + __half2float(h[j][1]);
                rsum[i][1] += __half2float(h[j][2]) + __half2float(h[j][3]);
            }
            uint4 w4;
            w4.x = hfcat(h[0][0], h[0][1]);   // row g,   k-lo
            w4.y = hfcat(h[0][2], h[0][3]);   // row g+8, k-lo
            w4.z = hfcat(h[1][0], h[1][1]);   // row g,   k-hi
            w4.w = hfcat(h[1][2], h[1][3]);   // row g+8, k-hi
            *(uint4*)&g_Pf[tile0 + (size_t)((i_blk * 4 + wv) * 128 + lane * 4)] = w4;
        }
    }

    #pragma unroll
    for (int i = 0; i < 2; i++)
        #pragma unroll
        for (int r = 0; r < 2; r++) {
            float v = rsum[i][r];
            v += __shfl_xor_sync(0xffffffffu, v, 1);
            v += __shfl_xor_sync(0xffffffffu, v, 2);
            rsum[i][r] = v;
        }
    if (c == 0) {
        #pragma unroll
        for (int i = 0; i < 2; i++) {
            sL[wv][wn * 32 + i * 16 + g]     = rsum[i][0];
            sL[wv][wn * 32 + i * 16 + g + 8] = rsum[i][1];
        }
    }
    __syncthreads();
    if (tid < 64)
        g_L[(size_t)b * Nn + n0 + tid] = sL[0][tid] + sL[1][tid] + sL[2][tid] + sL[3][tid];
}

// ===========================================================================
// PV GEMM on fp16 m16n8k16, packed fragments:
//   out[b][v][n] = (1/L[n]) * sum_m P[n][m] V[m][v]
// Block 128(n) x 128(v), warp 64x32 (2x4 warps), K-chunk 32, 2-stage.
// SMEM u32: A stages @ {0, 2048} (8KB), B @ {4096, 6144} (8KB). 32KB total.
// ===========================================================================
static constexpr int AV_BYTES = 32768;

__device__ __forceinline__ void av_stage(uint32_t sbase, int buf,
                                         const uint32_t* gA, const uint32_t* gB,
                                         int v0j, int ch) {
    const int t = threadIdx.x;
    const int mt = ch >> 1, half = ch & 1;
    const uint32_t sA = sbase + (buf ? 2048u : 0u) * 4;
    const uint32_t sB = sbase + (4096u + buf * 2048u) * 4;
    const uint32_t* gAt = gA + (size_t)mt * 4096 + half * 256;
    const uint32_t* gBt = gB + (size_t)mt * 16384 + (size_t)half * 2 * 4096 + (size_t)v0j * 64;
    #pragma unroll
    for (int p = 0; p < 2; p++) {   // A: 512 x 16B
        int id = t + 256 * p, i_blk = id >> 6, rem = id & 63;
        int kbl = rem >> 5, w = rem & 31;
        cp_async16(sA + (uint32_t)(i_blk * 256 + kbl * 128 + w * 4) * 4,
                   gAt + (size_t)i_blk * 512 + kbl * 128 + w * 4);
    }
    #pragma unroll
    for (int p = 0; p < 2; p++) {   // B: 512 x 16B
        int id = t + 256 * p, kbl = id >> 8, rem = id & 255;
        int vjl = rem >> 4, q = rem & 15;
        cp_async16(sB + (uint32_t)(kbl * 1024 + vjl * 64 + q * 4) * 4,
                   gBt + (size_t)kbl * 4096 + (size_t)vjl * 64 + q * 4);
    }
}

__global__ __launch_bounds__(256, 2) void av_mma_kernel(float* __restrict__ out) {
    extern __shared__ uint32_t smu[];
    const uint32_t sbase = smem_u32(smu);
    const int tid  = threadIdx.x;
    const int wid  = tid >> 5, lane = tid & 31;
    const int g = lane >> 2, c = lane & 3;
    const int wn = wid & 1, wv = wid >> 1;
    const int b  = blockIdx.z;
    const int nt = blockIdx.y;
    const int n0 = nt * 128;
    const int v0 = blockIdx.x * 128;

    const uint32_t* gA = g_Pf + (((size_t)b * 32 + nt) * 64) * 4096;
    const uint32_t* gB = g_Vh + ((size_t)b * 64) * 16384;

    float acc[4][4][4] = {};

    av_stage(sbase, 0, gA, gB, v0 >> 3, 0);
    cp_commit();

    for (int ch = 0; ch < 128; ch++) {
        const int cur = ch & 1;
        if (ch + 1 < 128) {
            av_stage(sbase, cur ^ 1, gA, gB, v0 >> 3, ch + 1);
            cp_commit();
            cp_wait1();
        } else {
            cp_wait0();
        }
        __syncthreads();

        const uint32_t* As = smu + cur * 2048;
        const uint32_t* Bs = smu + 4096 + cur * 2048;

        #pragma unroll
        for (int kbl = 0; kbl < 2; kbl++) {
            uint4 af[4];
            #pragma unroll
            for (int i = 0; i < 4; i++)
                af[i] = *(const uint4*)(As + (wn * 4 + i) * 256 + kbl * 128 + lane * 4);
            uint2 bfr[4];
            #pragma unroll
            for (int j = 0; j < 4; j++)
                bfr[j] = *(const uint2*)(Bs + kbl * 1024 + (wv * 4 + j) * 64 + lane * 2);
            #pragma unroll
            for (int i = 0; i < 4; i++)
                #pragma unroll
                for (int j = 0; j < 4; j++)
                    mma_f16(acc[i][j], (const uint32_t*)&af[i], (const uint32_t*)&bfr[j]);
        }
        __syncthreads();
    }

    #pragma unroll
    for (int i = 0; i < 4; i++) {
        const int n_lo = n0 + wn * 64 + i * 16 + g;
        const float linv_lo = 1.0f / g_L[(size_t)b * Nn + n_lo];
        const float linv_hi = 1.0f / g_L[(size_t)b * Nn + n_lo + 8];
        #pragma unroll
        for (int j = 0; j < 4; j++) {
            const int v = v0 + wv * 32 + j * 8 + c * 2;
            float* o0p = out + ((size_t)b * Vd + v)     * Nn + n_lo;
            float* o1p = out + ((size_t)b * Vd + v + 1) * Nn + n_lo;
            o0p[0] = acc[i][j][0] * linv_lo;
            o1p[0] = acc[i][j][1] * linv_lo;
            o0p[8] = acc[i][j][2] * linv_hi;
            o1p[8] = acc[i][j][3] * linv_hi;
        }
    }
}

// ===========================================================================
extern "C" void kernel_launch(void* const* d_in, const int* in_sizes, int n_in,
                              void* d_out, int out_size) {
    const float* x     = (const float*)d_in[0];
    const float* Wq    = (const float*)d_in[1];
    const float* bq    = (const float*)d_in[2];
    const float* Wk    = (const float*)d_in[3];
    const float* bk    = (const float*)d_in[4];
    const float* Wv    = (const float*)d_in[5];
    const float* gamma = (const float*)d_in[6];
    const float* beta  = (const float*)d_in[7];
    const float* mean  = (const float*)d_in[8];
    const float* var   = (const float*)d_in[9];
    float* out = (float*)d_out;

    static int smem_set = 0;
    if (!smem_set) {
        cudaFuncSetAttribute(qk_mma_kernel,
                             cudaFuncAttributeMaxDynamicSharedMemorySize, QK_BYTES);
        cudaFuncSetAttribute(maxpass_kernel,
                             cudaFuncAttributeMaxDynamicSharedMemorySize, MX_BYTES);
        cudaFuncSetAttribute(vproj_mma_kernel,
                             cudaFuncAttributeMaxDynamicSharedMemorySize, V_FLOATS * 4);
        cudaFuncSetAttribute(energy_mma_kernel,
                             cudaFuncAttributeMaxDynamicSharedMemorySize, E_BYTES);
        cudaFuncSetAttribute(av_mma_kernel,
                             cudaFuncAttributeMaxDynamicSharedMemorySize, AV_BYTES);
        smem_set = 1;
    }

    prep_kernel<<<1, 512>>>(gamma, beta, mean, var);
    wsplit_kernel<<<256, 256>>>(Wq, Wk);
    xsplit_kernel<<<dim3(Nn / 32, Cc / 32, Bn), 256>>>(x);

    qk_mma_kernel<<<dim3(Nn / 64, 1, Bn), 256, QK_BYTES>>>(bq, bk);
    vproj_mma_kernel<<<dim3(Vd / 128, Nn / 128, Bn), 256, V_FLOATS * 4>>>(x, Wv);

    maxpass_kernel<<<dim3(Nn / 64, Bn), 256, MX_BYTES>>>();
    energy_mma_kernel<<<dim3(Nn / 64, Bn), 256, E_BYTES>>>();

    av_mma_kernel<<<dim3(Vd / 128, Nn / 128, Bn), 256, AV_BYTES>>>(out);
}

// round 11
// speedup vs baseline: 1.9695x; 1.0469x over previous
#include <cuda_runtime.h>
#include <cuda_bf16.h>
#include <cuda_fp16.h>
#include <cstdint>
#include <cstddef>

static constexpr int Bn = 8;
static constexpr int Cc = 512;
static constexpr int Nn = 4096;   // H*W
static constexpr int Kd = 64;
static constexpr int Vd = 512;

// Scratch (device globals)
__device__ __nv_bfloat16 g_Xh[(size_t)Bn * Nn * Cc];   // x transposed [b][n][c] bf16 hi
__device__ __nv_bfloat16 g_Xl[(size_t)Bn * Nn * Cc];
__device__ __half        g_Xf[(size_t)Bn * Nn * Cc];   // x transposed [b][n][c] fp16
__device__ __nv_bfloat16 g_Wh[128 * Cc];               // [Wq;Wk]
__device__ __nv_bfloat16 g_Wl[128 * Cc];
__device__ __half        g_Wvf[Vd * Cc];               // Wv fp16 [v][c]
__device__ __nv_bfloat16 g_Qh[(size_t)Bn * Nn * Kd];
__device__ __nv_bfloat16 g_Ql[(size_t)Bn * Nn * Kd];
__device__ __nv_bfloat16 g_Kh[(size_t)Bn * Nn * Kd];
__device__ __nv_bfloat16 g_Kl[(size_t)Bn * Nn * Kd];
// V fp16 packed as av B-fragments: per [b][mt 0..63]: [kb 0..3][vj 0..63][lane][2] u32
__device__ uint32_t g_Vh[(size_t)Bn * 64 * 16384];
// P fp16 packed as av A-fragments: per [b][nt 0..31][mt 0..63]:
//   [i_blk 0..7][kb 0..3][lane 0..31][4] u32   (4096 u32 = 16KB per tile)
__device__ uint32_t g_Pf[(size_t)Bn * 32 * 64 * 4096];
__device__ float g_M [(size_t)Bn * Nn];        // row maxes (approx)
__device__ float g_L [(size_t)Bn * Nn];        // row sums of shifted exps
__device__ float g_scl[Vd];
__device__ float g_shf[Vd];

// ===========================================================================
// Helpers (portable ISA: sm_80-class mma.sync + cp.async only)
// ===========================================================================
__device__ __forceinline__ uint32_t smem_u32(const void* p) {
    uint32_t a;
    asm("{ .reg .u64 t; cvta.to.shared.u64 t, %1; cvt.u32.u64 %0, t; }" : "=r"(a) : "l"(p));
    return a;
}
__device__ __forceinline__ void cp_async16(uint32_t saddr, const void* gaddr) {
    asm volatile("cp.async.ca.shared.global [%0], [%1], 16;"
                 :: "r"(saddr), "l"(gaddr) : "memory");
}
__device__ __forceinline__ void cp_commit() {
    asm volatile("cp.async.commit_group;" ::: "memory");
}
__device__ __forceinline__ void cp_wait1() {
    asm volatile("cp.async.wait_group 1;" ::: "memory");
}
__device__ __forceinline__ void cp_wait0() {
    asm volatile("cp.async.wait_group 0;" ::: "memory");
}
__device__ __forceinline__ void mma_bf16(float* d, const uint32_t* a, const uint32_t* b) {
    asm volatile(
        "mma.sync.aligned.m16n8k16.row.col.f32.bf16.bf16.f32 "
        "{%0,%1,%2,%3}, {%4,%5,%6,%7}, {%8,%9}, {%0,%1,%2,%3};"
        : "+f"(d[0]), "+f"(d[1]), "+f"(d[2]), "+f"(d[3])
        : "r"(a[0]), "r"(a[1]), "r"(a[2]), "r"(a[3]), "r"(b[0]), "r"(b[1]));
}
__device__ __forceinline__ void mma_f16(float* d, const uint32_t* a, const uint32_t* b) {
    asm volatile(
        "mma.sync.aligned.m16n8k16.row.col.f32.f16.f16.f32 "
        "{%0,%1,%2,%3}, {%4,%5,%6,%7}, {%8,%9}, {%0,%1,%2,%3};"
        : "+f"(d[0]), "+f"(d[1]), "+f"(d[2]), "+f"(d[3])
        : "r"(a[0]), "r"(a[1]), "r"(a[2]), "r"(a[3]), "r"(b[0]), "r"(b[1]));
}
__device__ __forceinline__ uint32_t lds_u32(const char* p) { return *(const uint32_t*)p; }
__device__ __forceinline__ uint32_t bfcat(__nv_bfloat16 lo, __nv_bfloat16 hi) {
    __nv_bfloat162 t; t.x = lo; t.y = hi;
    return *(uint32_t*)&t;
}
__device__ __forceinline__ uint32_t hfcat(__half lo, __half hi) {
    __half2 t; t.x = lo; t.y = hi;
    return *(uint32_t*)&t;
}

// ===========================================================================
// BN scale/shift precompute
// ===========================================================================
__global__ void prep_kernel(const float* __restrict__ gamma, const float* __restrict__ beta,
                            const float* __restrict__ mean,  const float* __restrict__ var) {
    int i = threadIdx.x;
    if (i < Vd) {
        float s = gamma[i] * rsqrtf(var[i] + 1e-5f);
        g_scl[i] = s;
        g_shf[i] = beta[i] - mean[i] * s;
    }
}

// ===========================================================================
// W split: [Wq;Wk] -> bf16 hi/lo
// ===========================================================================
__global__ __launch_bounds__(256) void wsplit_kernel(const float* __restrict__ Wq,
                                                     const float* __restrict__ Wk) {
    int id = blockIdx.x * 256 + threadIdx.x;
    int o = id >> 9, cc = id & 511;
    float v = (o < 64) ? Wq[o * Cc + cc] : Wk[(o - 64) * Cc + cc];
    __nv_bfloat16 h = __float2bfloat16(v);
    g_Wh[id] = h;
    g_Wl[id] = __float2bfloat16(v - __bfloat162float(h));
}

// ===========================================================================
// Wv -> fp16
// ===========================================================================
__global__ __launch_bounds__(256) void wvhalf_kernel(const float* __restrict__ Wv) {
    int id = blockIdx.x * 256 + threadIdx.x;     // 512*512
    g_Wvf[id] = __float2half(Wv[id]);
}

// ===========================================================================
// X split + transpose: x[b][c][n] fp32 -> [b][n][c]: bf16 hi/lo + fp16
// ===========================================================================
__global__ __launch_bounds__(256) void xsplit_kernel(const float* __restrict__ x) {
    __shared__ float t[32][33];
    const int b = blockIdx.z, n0 = blockIdx.x * 32, c0 = blockIdx.y * 32;
    const int tx = threadIdx.x & 31, ty = threadIdx.x >> 5;
    #pragma unroll
    for (int p = 0; p < 4; p++)
        t[ty + 8 * p][tx] = x[((size_t)b * Cc + c0 + ty + 8 * p) * Nn + n0 + tx];
    __syncthreads();
    #pragma unroll
    for (int p = 0; p < 4; p++) {
        float v = t[tx][ty + 8 * p];
        __nv_bfloat16 h = __float2bfloat16(v);
        __nv_bfloat16 l = __float2bfloat16(v - __bfloat162float(h));
        size_t idx = ((size_t)b * Nn + n0 + ty + 8 * p) * Cc + c0 + tx;
        g_Xh[idx] = h;
        g_Xl[idx] = l;
        g_Xf[idx] = __float2half(v);
    }
}

// ===========================================================================
// Q+K projection on mma.sync bf16 (3-term split)   (unchanged from R10)
// ===========================================================================
static constexpr int QK_XH0 = 0,     QK_XH1 = 5120;
static constexpr int QK_XL0 = 10240, QK_XL1 = 15360;
static constexpr int QK_WH0 = 20480, QK_WH1 = 30720;
static constexpr int QK_WL0 = 40960, QK_WL1 = 51200;
static constexpr int QK_BYTES = 61440;

__device__ __forceinline__ void qk_stage(uint32_t sbase, int buf, int b, int n0, int kc) {
    const int t = threadIdx.x;
    const uint32_t xh = sbase + (buf ? QK_XH1 : QK_XH0);
    const uint32_t xl = sbase + (buf ? QK_XL1 : QK_XL0);
    const uint32_t wh = sbase + (buf ? QK_WH1 : QK_WH0);
    const uint32_t wl = sbase + (buf ? QK_WL1 : QK_WL0);
    {
        int r = t >> 2, c4 = t & 3;
        size_t src = ((size_t)b * Nn + n0 + r) * Cc + kc * 32 + c4 * 8;
        cp_async16(xh + r * 80 + c4 * 16, g_Xh + src);
        cp_async16(xl + r * 80 + c4 * 16, g_Xl + src);
    }
    #pragma unroll
    for (int p = 0; p < 2; p++) {
        int id = t + 256 * p, r = id >> 2, c4 = id & 3;
        size_t src = (size_t)r * Cc + kc * 32 + c4 * 8;
        cp_async16(wh + r * 80 + c4 * 16, g_Wh + src);
        cp_async16(wl + r * 80 + c4 * 16, g_Wl + src);
    }
}

__global__ __launch_bounds__(256) void qk_mma_kernel(const float* __restrict__ bq,
                                                     const float* __restrict__ bk) {
    extern __shared__ char smc[];
    const uint32_t sbase = smem_u32(smc);
    const int tid = threadIdx.x;
    const int wid = tid >> 5, lane = tid & 31;
    const int g = lane >> 2, c = lane & 3;
    const int wn = wid & 1, wo = wid >> 1;
    const int b  = blockIdx.z;
    const int n0 = blockIdx.x * 64;

    float acc[2][4][4] = {};

    qk_stage(sbase, 0, b, n0, 0);
    cp_commit();

    for (int kc = 0; kc < 16; kc++) {
        const int cur = kc & 1;
        if (kc + 1 < 16) {
            qk_stage(sbase, cur ^ 1, b, n0, kc + 1);
            cp_commit();
            cp_wait1();
        } else {
            cp_wait0();
        }
        __syncthreads();

        const char* XH = smc + (cur ? QK_XH1 : QK_XH0);
        const char* XL = smc + (cur ? QK_XL1 : QK_XL0);
        const char* WH = smc + (cur ? QK_WH1 : QK_WH0);
        const char* WL = smc + (cur ? QK_WL1 : QK_WL0);

        #pragma unroll
        for (int ks = 0; ks < 2; ks++) {
            uint32_t ah[2][4], al[2][4];
            #pragma unroll
            for (int i = 0; i < 2; i++) {
                const int off = (wn * 32 + i * 16 + g) * 80 + ks * 32 + c * 4;
                ah[i][0] = lds_u32(XH + off);
                ah[i][1] = lds_u32(XH + off + 8 * 80);
                ah[i][2] = lds_u32(XH + off + 16);
                ah[i][3] = lds_u32(XH + off + 8 * 80 + 16);
                al[i][0] = lds_u32(XL + off);
                al[i][1] = lds_u32(XL + off + 8 * 80);
                al[i][2] = lds_u32(XL + off + 16);
                al[i][3] = lds_u32(XL + off + 8 * 80 + 16);
            }
            uint32_t bh[4][2], bl[4][2];
            #pragma unroll
            for (int j = 0; j < 4; j++) {
                const int off = (wo * 32 + j * 8 + g) * 80 + ks * 32 + c * 4;
                bh[j][0] = lds_u32(WH + off);
                bh[j][1] = lds_u32(WH + off + 16);
                bl[j][0] = lds_u32(WL + off);
                bl[j][1] = lds_u32(WL + off + 16);
            }
            #pragma unroll
            for (int i = 0; i < 2; i++)
                #pragma unroll
                for (int j = 0; j < 4; j++) {
                    mma_bf16(acc[i][j], ah[i], bh[j]);
                    mma_bf16(acc[i][j], ah[i], bl[j]);
                    mma_bf16(acc[i][j], al[i], bh[j]);
                }
        }
        __syncthreads();
    }

    const int which = wo >> 1;
    __nv_bfloat16* dh = which ? g_Kh : g_Qh;
    __nv_bfloat16* dl = which ? g_Kl : g_Ql;
    const float* bias = which ? bk : bq;
    #pragma unroll
    for (int i = 0; i < 2; i++) {
        const int n_lo = n0 + wn * 32 + i * 16 + g;
        #pragma unroll
        for (int j = 0; j < 4; j++) {
            const int o = (wo * 32 + j * 8 + 2 * c) & 63;
            const float b0 = bias[o], b1 = bias[o + 1];
            float v00 = acc[i][j][0] + b0, v01 = acc[i][j][1] + b1;
            float v10 = acc[i][j][2] + b0, v11 = acc[i][j][3] + b1;
            __nv_bfloat16 h00 = __float2bfloat16(v00), h01 = __float2bfloat16(v01);
            __nv_bfloat16 h10 = __float2bfloat16(v10), h11 = __float2bfloat16(v11);
            __nv_bfloat16 l00 = __float2bfloat16(v00 - __bfloat162float(h00));
            __nv_bfloat16 l01 = __float2bfloat16(v01 - __bfloat162float(h01));
            __nv_bfloat16 l10 = __float2bfloat16(v10 - __bfloat162float(h10));
            __nv_bfloat16 l11 = __float2bfloat16(v11 - __bfloat162float(h11));
            size_t r0 = ((size_t)b * Nn + n_lo) * Kd + o;
            size_t r1 = ((size_t)b * Nn + n_lo + 8) * Kd + o;
            *(uint32_t*)&dh[r0] = bfcat(h00, h01);
            *(uint32_t*)&dh[r1] = bfcat(h10, h11);
            *(uint32_t*)&dl[r0] = bfcat(l00, l01);
            *(uint32_t*)&dl[r1] = bfcat(l10, l11);
        }
    }
}

// ===========================================================================
// Max pass: M[b][n] ~= max_m (q.k) via hi-only bf16 QK^T.   (unchanged)
// ===========================================================================
static constexpr int MX_QH  = 0;
static constexpr int MX_KH0 = 9216;
static constexpr int MX_KH1 = 18432;
static constexpr int MX_BYTES = 27648;

__global__ __launch_bounds__(256) void maxpass_kernel() {
    extern __shared__ char smc[];
    __shared__ float sM[4][64];
    const uint32_t sbase = smem_u32(smc);
    const int tid = threadIdx.x;
    const int wid = tid >> 5, lane = tid & 31;
    const int g = lane >> 2, c = lane & 3;
    const int wn = wid & 1, wv = wid >> 1;
    const int b  = blockIdx.y;
    const int n0 = blockIdx.x * 64;

    const size_t qoff = ((size_t)b * Nn + n0) * Kd;
    const size_t koff = (size_t)b * Nn * Kd;

    #pragma unroll
    for (int p = 0; p < 2; p++) {
        int id = tid + 256 * p, r = id >> 3, c8 = id & 7;
        cp_async16(sbase + MX_QH + r * 144 + c8 * 16, g_Qh + qoff + (size_t)r * Kd + c8 * 8);
    }
    {
        int r = tid >> 2, c8 = (tid & 3) * 2;
        cp_async16(sbase + MX_KH0 + r * 144 + c8 * 16, g_Kh + koff + (size_t)r * Kd + c8 * 8);
        cp_async16(sbase + MX_KH0 + r * 144 + (c8 + 1) * 16, g_Kh + koff + (size_t)r * Kd + (c8 + 1) * 8);
    }
    cp_commit();

    float mx[2][2] = { { -1e30f, -1e30f }, { -1e30f, -1e30f } };

    for (int mc = 0; mc < 64; mc++) {
        const int cur = mc & 1;
        if (mc + 1 < 64) {
            const uint32_t kh = sbase + ((mc + 1) & 1 ? MX_KH1 : MX_KH0);
            int r = tid >> 2, c8 = (tid & 3) * 2;
            cp_async16(kh + r * 144 + c8 * 16,
                       g_Kh + koff + (size_t)((mc + 1) * 64 + r) * Kd + c8 * 8);
            cp_async16(kh + r * 144 + (c8 + 1) * 16,
                       g_Kh + koff + (size_t)((mc + 1) * 64 + r) * Kd + (c8 + 1) * 8);
            cp_commit();
            cp_wait1();
        } else {
            cp_wait0();
        }
        __syncthreads();

        const char* QH = smc + MX_QH;
        const char* KH = smc + (cur ? MX_KH1 : MX_KH0);

        float acc[2][2][4] = {};
        #pragma unroll
        for (int ks = 0; ks < 4; ks++) {
            uint32_t ah[2][4];
            #pragma unroll
            for (int i = 0; i < 2; i++) {
                const int off = (wn * 32 + i * 16 + g) * 144 + ks * 32 + c * 4;
                ah[i][0] = lds_u32(QH + off);
                ah[i][1] = lds_u32(QH + off + 8 * 144);
                ah[i][2] = lds_u32(QH + off + 16);
                ah[i][3] = lds_u32(QH + off + 8 * 144 + 16);
            }
            uint32_t bh[2][2];
            #pragma unroll
            for (int j = 0; j < 2; j++) {
                const int off = (wv * 16 + j * 8 + g) * 144 + ks * 32 + c * 4;
                bh[j][0] = lds_u32(KH + off);
                bh[j][1] = lds_u32(KH + off + 16);
            }
            #pragma unroll
            for (int i = 0; i < 2; i++)
                #pragma unroll
                for (int j = 0; j < 2; j++)
                    mma_bf16(acc[i][j], ah[i], bh[j]);
        }
        __syncthreads();

        #pragma unroll
        for (int i = 0; i < 2; i++)
            #pragma unroll
            for (int j = 0; j < 2; j++) {
                mx[i][0] = fmaxf(mx[i][0], fmaxf(acc[i][j][0], acc[i][j][1]));
                mx[i][1] = fmaxf(mx[i][1], fmaxf(acc[i][j][2], acc[i][j][3]));
            }
    }

    #pragma unroll
    for (int i = 0; i < 2; i++)
        #pragma unroll
        for (int r = 0; r < 2; r++) {
            float v = mx[i][r];
            v = fmaxf(v, __shfl_xor_sync(0xffffffffu, v, 1));
            v = fmaxf(v, __shfl_xor_sync(0xffffffffu, v, 2));
            mx[i][r] = v;
        }
    if (c == 0) {
        #pragma unroll
        for (int i = 0; i < 2; i++) {
            sM[wv][wn * 32 + i * 16 + g]     = mx[i][0];
            sM[wv][wn * 32 + i * 16 + g + 8] = mx[i][1];
        }
    }
    __syncthreads();
    if (tid < 64)
        g_M[(size_t)b * Nn + n0 + tid] =
            fmaxf(fmaxf(sM[0][tid], sM[1][tid]), fmaxf(sM[2][tid], sM[3][tid]));
}

// ===========================================================================
// V projection on single-pass fp16 mma.sync (same 11-bit mantissa as tf32):
//   D[v][m] = sum_c Wv[v][c] * X[m][c]; A = Wv fp16 [v][c], B = X fp16 [m][c].
// Tile 128(v) x 128(m) x 32(c); warps wn -> v 64-block, wv -> m 32-block.
// SMEM rows 32 fp16 = 64B padded to 80B (conflict-free, same as qk).
// ===========================================================================
static constexpr int VP_W0 = 0,     VP_W1 = 10240;
static constexpr int VP_X0 = 20480, VP_X1 = 30720;
static constexpr int VP_BYTES = 40960;

__device__ __forceinline__ void vproj_stage(uint32_t sbase, int buf, int b,
                                            int m0, int v0, int kc) {
    const int t = threadIdx.x;
    const uint32_t sW = sbase + (buf ? VP_W1 : VP_W0);
    const uint32_t sX = sbase + (buf ? VP_X1 : VP_X0);
    #pragma unroll
    for (int p = 0; p < 2; p++) {                 // W: 128 rows x 4 x 16B
        int id = t + 256 * p, r = id >> 2, c4 = id & 3;
        cp_async16(sW + r * 80 + c4 * 16,
                   g_Wvf + (size_t)(v0 + r) * Cc + kc * 32 + c4 * 8);
    }
    #pragma unroll
    for (int p = 0; p < 2; p++) {                 // X: 128 rows x 4 x 16B
        int id = t + 256 * p, r = id >> 2, c4 = id & 3;
        cp_async16(sX + r * 80 + c4 * 16,
                   g_Xf + ((size_t)b * Nn + m0 + r) * Cc + kc * 32 + c4 * 8);
    }
}

__global__ __launch_bounds__(256) void vproj_mma_kernel() {
    extern __shared__ char smc[];
    const uint32_t sbase = smem_u32(smc);
    const int tid = threadIdx.x;
    const int wid = tid >> 5, lane = tid & 31;
    const int g = lane >> 2, c = lane & 3;
    const int wn = wid & 1, wv = wid >> 1;
    const int b  = blockIdx.z;
    const int m0 = blockIdx.y * 128;
    const int v0 = blockIdx.x * 128;

    float acc[4][4][4] = {};   // [i: v16][j: m8][frag]

    vproj_stage(sbase, 0, b, m0, v0, 0);
    cp_commit();

    for (int kc = 0; kc < Cc / 32; kc++) {
        const int cur = kc & 1;
        if (kc + 1 < Cc / 32) {
            vproj_stage(sbase, cur ^ 1, b, m0, v0, kc + 1);
            cp_commit();
            cp_wait1();
        } else {
            cp_wait0();
        }
        __syncthreads();

        const char* Ws = smc + (cur ? VP_W1 : VP_W0);
        const char* Xs = smc + (cur ? VP_X1 : VP_X0);

        #pragma unroll
        for (int ks = 0; ks < 2; ks++) {
            uint32_t af[4][4];
            #pragma unroll
            for (int i = 0; i < 4; i++) {     // A = W rows v
                const int off = (wn * 64 + i * 16 + g) * 80 + ks * 32 + c * 4;
                af[i][0] = lds_u32(Ws + off);
                af[i][1] = lds_u32(Ws + off + 8 * 80);
                af[i][2] = lds_u32(Ws + off + 16);
                af[i][3] = lds_u32(Ws + off + 8 * 80 + 16);
            }
            uint32_t bf[4][2];
            #pragma unroll
            for (int j = 0; j < 4; j++) {     // B = X rows m
                const int off = (wv * 32 + j * 8 + g) * 80 + ks * 32 + c * 4;
                bf[j][0] = lds_u32(Xs + off);
                bf[j][1] = lds_u32(Xs + off + 16);
            }
            #pragma unroll
            for (int i = 0; i < 4; i++)
                #pragma unroll
                for (int j = 0; j < 4; j++)
                    mma_f16(acc[i][j], af[i], bf[j]);
        }
        __syncthreads();
    }

    // Epilogue: BN+ReLU (per v row), fp16, write packed B-fragments.
    const int mt = blockIdx.y * 2 + (wv >> 1);
    uint32_t* base = g_Vh + ((size_t)b * 64 + mt) * 16384;
    #pragma unroll
    for (int i = 0; i < 4; i++) {
        const int vg = v0 + wn * 64 + i * 16 + g;
        const float sg = g_scl[vg],     hg = g_shf[vg];
        const float s8 = g_scl[vg + 8], h8 = g_shf[vg + 8];
        const int vj = vg >> 3;
        #pragma unroll
        for (int j = 0; j < 4; j++) {
            const int kb = ((wv * 32 + j * 8) >> 4) & 3;
            const int lohi = j & 1;
            __half a0 = __float2half(fmaxf(fmaf(acc[i][j][0], sg, hg), 0.f));
            __half a1 = __float2half(fmaxf(fmaf(acc[i][j][1], sg, hg), 0.f));
            __half a2 = __float2half(fmaxf(fmaf(acc[i][j][2], s8, h8), 0.f));
            __half a3 = __float2half(fmaxf(fmaf(acc[i][j][3], s8, h8), 0.f));
            base[(size_t)kb * 4096 + (size_t)vj * 64 + lane * 2 + lohi]       = hfcat(a0, a1);
            base[(size_t)kb * 4096 + (size_t)(vj + 1) * 64 + lane * 2 + lohi] = hfcat(a2, a3);
        }
    }
}

// ===========================================================================
// Energy on mma.sync BF16 (3-term); epilogue: exp(l - M[n]) -> fp16 packed
// A-fragment tiles g_Pf, + row sums g_L.   (unchanged from R10)
// ===========================================================================
static constexpr int E_QH  = 0;
static constexpr int E_QL  = 9216;
static constexpr int E_KH0 = 18432;
static constexpr int E_KH1 = 27648;
static constexpr int E_KL0 = 36864;
static constexpr int E_KL1 = 46080;
static constexpr int E_BYTES = 55296;

__global__ __launch_bounds__(256) void energy_mma_kernel() {
    extern __shared__ char smc[];
    __shared__ float sL[4][64];
    const uint32_t sbase = smem_u32(smc);
    const int tid = threadIdx.x;
    const int wid = tid >> 5, lane = tid & 31;
    const int g = lane >> 2, c = lane & 3;
    const int wn = wid & 1, wv = wid >> 1;
    const int b  = blockIdx.y;
    const int n0 = blockIdx.x * 64;
    const int nt = blockIdx.x >> 1;
    const int half = blockIdx.x & 1;

    const size_t qoff = ((size_t)b * Nn + n0) * Kd;
    const size_t koff = (size_t)b * Nn * Kd;

    #pragma unroll
    for (int p = 0; p < 2; p++) {
        int id = tid + 256 * p, r = id >> 3, c8 = id & 7;
        cp_async16(sbase + E_QH + r * 144 + c8 * 16, g_Qh + qoff + (size_t)r * Kd + c8 * 8);
        cp_async16(sbase + E_QL + r * 144 + c8 * 16, g_Ql + qoff + (size_t)r * Kd + c8 * 8);
    }
    #pragma unroll
    for (int p = 0; p < 2; p++) {
        int id = tid + 256 * p, r = id >> 3, c8 = id & 7;
        cp_async16(sbase + E_KH0 + r * 144 + c8 * 16, g_Kh + koff + (size_t)r * Kd + c8 * 8);
        cp_async16(sbase + E_KL0 + r * 144 + c8 * 16, g_Kl + koff + (size_t)r * Kd + c8 * 8);
    }
    cp_commit();

    float Mv[2][2];
    #pragma unroll
    for (int i = 0; i < 2; i++) {
        Mv[i][0] = g_M[(size_t)b * Nn + n0 + wn * 32 + i * 16 + g];
        Mv[i][1] = g_M[(size_t)b * Nn + n0 + wn * 32 + i * 16 + g + 8];
    }

    float rsum[2][2] = {};

    for (int mc = 0; mc < 64; mc++) {
        const int cur = mc & 1;
        if (mc + 1 < 64) {
            const uint32_t kh = sbase + ((mc + 1) & 1 ? E_KH1 : E_KH0);
            const uint32_t kl = sbase + ((mc + 1) & 1 ? E_KL1 : E_KL0);
            #pragma unroll
            for (int p = 0; p < 2; p++) {
                int id = tid + 256 * p, r = id >> 3, c8 = id & 7;
                cp_async16(kh + r * 144 + c8 * 16,
                           g_Kh + koff + (size_t)((mc + 1) * 64 + r) * Kd + c8 * 8);
                cp_async16(kl + r * 144 + c8 * 16,
                           g_Kl + koff + (size_t)((mc + 1) * 64 + r) * Kd + c8 * 8);
            }
            cp_commit();
            cp_wait1();
        } else {
            cp_wait0();
        }
        __syncthreads();

        const char* QH = smc + E_QH;
        const char* QL = smc + E_QL;
        const char* KH = smc + (cur ? E_KH1 : E_KH0);
        const char* KL = smc + (cur ? E_KL1 : E_KL0);

        float acc[2][2][4] = {};
        #pragma unroll
        for (int ks = 0; ks < 4; ks++) {
            uint32_t ah[2][4], al[2][4];
            #pragma unroll
            for (int i = 0; i < 2; i++) {
                const int off = (wn * 32 + i * 16 + g) * 144 + ks * 32 + c * 4;
                ah[i][0] = lds_u32(QH + off);
                ah[i][1] = lds_u32(QH + off + 8 * 144);
                ah[i][2] = lds_u32(QH + off + 16);
                ah[i][3] = lds_u32(QH + off + 8 * 144 + 16);
                al[i][0] = lds_u32(QL + off);
                al[i][1] = lds_u32(QL + off + 8 * 144);
                al[i][2] = lds_u32(QL + off + 16);
                al[i][3] = lds_u32(QL + off + 8 * 144 + 16);
            }
            uint32_t bh[2][2], bl[2][2];
            #pragma unroll
            for (int j = 0; j < 2; j++) {
                const int off = (wv * 16 + j * 8 + g) * 144 + ks * 32 + c * 4;
                bh[j][0] = lds_u32(KH + off);
                bh[j][1] = lds_u32(KH + off + 16);
                bl[j][0] = lds_u32(KL + off);
                bl[j][1] = lds_u32(KL + off + 16);
            }
            #pragma unroll
            for (int i = 0; i < 2; i++)
                #pragma unroll
                for (int j = 0; j < 2; j++) {
                    mma_bf16(acc[i][j], ah[i], bh[j]);
                    mma_bf16(acc[i][j], ah[i], bl[j]);
                    mma_bf16(acc[i][j], al[i], bh[j]);
                }
        }
        __syncthreads();

        const size_t tile0 = (((size_t)b * 32 + nt) * 64 + mc) * 4096;
        #pragma unroll
        for (int i = 0; i < 2; i++) {
            const int i_blk = half * 4 + wn * 2 + i;
            __half h[2][4];
            #pragma unroll
            for (int j = 0; j < 2; j++) {
                h[j][0] = __float2half(__expf(acc[i][j][0] - Mv[i][0]));
                h[j][1] = __float2half(__expf(acc[i][j][1] - Mv[i][0]));
                h[j][2] = __float2half(__expf(acc[i][j][2] - Mv[i][1]));
                h[j][3] = __float2half(__expf(acc[i][j][3] - Mv[i][1]));
                rsum[i][0] += __half2float(h[j][0]) + __half2float(h[j][1]);
                rsum[i][1] += __half2float(h[j][2]) + __half2float(h[j][3]);
            }
            uint4 w4;
            w4.x = hfcat(h[0][0], h[0][1]);
            w4.y = hfcat(h[0][2], h[0][3]);
            w4.z = hfcat(h[1][0], h[1][1]);
            w4.w = hfcat(h[1][2], h[1][3]);
            *(uint4*)&g_Pf[tile0 + (size_t)((i_blk * 4 + wv) * 128 + lane * 4)] = w4;
        }
    }

    #pragma unroll
    for (int i = 0; i < 2; i++)
        #pragma unroll
        for (int r = 0; r < 2; r++) {
            float v = rsum[i][r];
            v += __shfl_xor_sync(0xffffffffu, v, 1);
            v += __shfl_xor_sync(0xffffffffu, v, 2);
            rsum[i][r] = v;
        }
    if (c == 0) {
        #pragma unroll
        for (int i = 0; i < 2; i++) {
            sL[wv][wn * 32 + i * 16 + g]     = rsum[i][0];
            sL[wv][wn * 32 + i * 16 + g + 8] = rsum[i][1];
        }
    }
    __syncthreads();
    if (tid < 64)
        g_L[(size_t)b * Nn + n0 + tid] = sL[0][tid] + sL[1][tid] + sL[2][tid] + sL[3][tid];
}

// ===========================================================================
// PV GEMM on fp16 m16n8k16, packed fragments, K-chunk 64 (full mt tile):
//   out[b][v][n] = (1/L[n]) * sum_m P[n][m] V[m][v]
// Block 128(n) x 128(v), warp 64x32 (2x4 warps), 2-stage.
// SMEM u32: A stages @ {0, 4096} (16KB), B @ {8192, 12288} (16KB). 64KB.
// ===========================================================================
static constexpr int AV_BYTES = 65536;

__device__ __forceinline__ void av_stage(uint32_t sbase, int buf,
                                         const uint32_t* gA, const uint32_t* gB,
                                         int v0j, int mt) {
    const int t = threadIdx.x;
    const uint32_t sA = sbase + (buf ? 4096u : 0u) * 4;
    const uint32_t sB = sbase + (8192u + buf * 4096u) * 4;
    const uint32_t* gAt = gA + (size_t)mt * 4096;
    const uint32_t* gBt = gB + (size_t)mt * 16384 + (size_t)v0j * 64;
    #pragma unroll
    for (int p = 0; p < 4; p++) {   // A: linear 1024 x 16B
        int id = t + 256 * p;
        cp_async16(sA + (uint32_t)id * 16, gAt + id * 4);
    }
    #pragma unroll
    for (int p = 0; p < 4; p++) {   // B: 4 kb x 16 vj x 64 u32
        int id = t + 256 * p, kb = id >> 8, rem = id & 255;
        int vjl = rem >> 4, q = rem & 15;
        cp_async16(sB + (uint32_t)(kb * 1024 + vjl * 64 + q * 4) * 4,
                   gBt + (size_t)kb * 4096 + (size_t)vjl * 64 + q * 4);
    }
}

__global__ __launch_bounds__(256, 2) void av_mma_kernel(float* __restrict__ out) {
    extern __shared__ uint32_t smu[];
    const uint32_t sbase = smem_u32(smu);
    const int tid  = threadIdx.x;
    const int wid  = tid >> 5, lane = tid & 31;
    const int g = lane >> 2, c = lane & 3;
    const int wn = wid & 1, wv = wid >> 1;
    const int b  = blockIdx.z;
    const int nt = blockIdx.y;
    const int n0 = nt * 128;
    const int v0 = blockIdx.x * 128;

    const uint32_t* gA = g_Pf + (((size_t)b * 32 + nt) * 64) * 4096;
    const uint32_t* gB = g_Vh + ((size_t)b * 64) * 16384;

    float acc[4][4][4] = {};

    av_stage(sbase, 0, gA, gB, v0 >> 3, 0);
    cp_commit();

    for (int mt = 0; mt < 64; mt++) {
        const int cur = mt & 1;
        if (mt + 1 < 64) {
            av_stage(sbase, cur ^ 1, gA, gB, v0 >> 3, mt + 1);
            cp_commit();
            cp_wait1();
        } else {
            cp_wait0();
        }
        __syncthreads();

        const uint32_t* As = smu + cur * 4096;
        const uint32_t* Bs = smu + 8192 + cur * 4096;

        #pragma unroll
        for (int kb = 0; kb < 4; kb++) {
            uint4 af[4];
            #pragma unroll
            for (int i = 0; i < 4; i++)
                af[i] = *(const uint4*)(As + (wn * 4 + i) * 512 + kb * 128 + lane * 4);
            uint2 bfr[4];
            #pragma unroll
            for (int j = 0; j < 4; j++)
                bfr[j] = *(const uint2*)(Bs + kb * 1024 + (wv * 4 + j) * 64 + lane * 2);
            #pragma unroll
            for (int i = 0; i < 4; i++)
                #pragma unroll
                for (int j = 0; j < 4; j++)
                    mma_f16(acc[i][j], (const uint32_t*)&af[i], (const uint32_t*)&bfr[j]);
        }
        __syncthreads();
    }

    #pragma unroll
    for (int i = 0; i < 4; i++) {
        const int n_lo = n0 + wn * 64 + i * 16 + g;
        const float linv_lo = 1.0f / g_L[(size_t)b * Nn + n_lo];
        const float linv_hi = 1.0f / g_L[(size_t)b * Nn + n_lo + 8];
        #pragma unroll
        for (int j = 0; j < 4; j++) {
            const int v = v0 + wv * 32 + j * 8 + c * 2;
            float* o0p = out + ((size_t)b * Vd + v)     * Nn + n_lo;
            float* o1p = out + ((size_t)b * Vd + v + 1) * Nn + n_lo;
            o0p[0] = acc[i][j][0] * linv_lo;
            o1p[0] = acc[i][j][1] * linv_lo;
            o0p[8] = acc[i][j][2] * linv_hi;
            o1p[8] = acc[i][j][3] * linv_hi;
        }
    }
}

// ===========================================================================
extern "C" void kernel_launch(void* const* d_in, const int* in_sizes, int n_in,
                              void* d_out, int out_size) {
    const float* x     = (const float*)d_in[0];
    const float* Wq    = (const float*)d_in[1];
    const float* bq    = (const float*)d_in[2];
    const float* Wk    = (const float*)d_in[3];
    const float* bk    = (const float*)d_in[4];
    const float* Wv    = (const float*)d_in[5];
    const float* gamma = (const float*)d_in[6];
    const float* beta  = (const float*)d_in[7];
    const float* mean  = (const float*)d_in[8];
    const float* var   = (const float*)d_in[9];
    float* out = (float*)d_out;

    static int smem_set = 0;
    if (!smem_set) {
        cudaFuncSetAttribute(qk_mma_kernel,
                             cudaFuncAttributeMaxDynamicSharedMemorySize, QK_BYTES);
        cudaFuncSetAttribute(maxpass_kernel,
                             cudaFuncAttributeMaxDynamicSharedMemorySize, MX_BYTES);
        cudaFuncSetAttribute(vproj_mma_kernel,
                             cudaFuncAttributeMaxDynamicSharedMemorySize, VP_BYTES);
        cudaFuncSetAttribute(energy_mma_kernel,
                             cudaFuncAttributeMaxDynamicSharedMemorySize, E_BYTES);
        cudaFuncSetAttribute(av_mma_kernel,
                             cudaFuncAttributeMaxDynamicSharedMemorySize, AV_BYTES);
        smem_set = 1;
    }

    prep_kernel<<<1, 512>>>(gamma, beta, mean, var);
    wsplit_kernel<<<256, 256>>>(Wq, Wk);
    wvhalf_kernel<<<1024, 256>>>(Wv);
    xsplit_kernel<<<dim3(Nn / 32, Cc / 32, Bn), 256>>>(x);

    qk_mma_kernel<<<dim3(Nn / 64, 1, Bn), 256, QK_BYTES>>>(bq, bk);
    vproj_mma_kernel<<<dim3(Vd / 128, Nn / 128, Bn), 256, VP_BYTES>>>();

    maxpass_kernel<<<dim3(Nn / 64, Bn), 256, MX_BYTES>>>();
    energy_mma_kernel<<<dim3(Nn / 64, Bn), 256, E_BYTES>>>();

    av_mma_kernel<<<dim3(Vd / 128, Nn / 128, Bn), 256, AV_BYTES>>>(out);
}